// round 2
// baseline (speedup 1.0000x reference)
#include <cuda_runtime.h>
#include <math.h>

#define B_   4
#define S_   2048
#define D_   1024
#define H_   16
#define HD_  64
#define N3_  3072   // 3 * D_

// Scratch for projected K, Q, V in [B, H, S, hd] layout (static device
// globals: allocation-free per harness rules). 32 MB each.
__device__ float g_k[(size_t)B_ * H_ * S_ * HD_];
__device__ float g_q[(size_t)B_ * H_ * S_ * HD_];
__device__ float g_v[(size_t)B_ * H_ * S_ * HD_];

// ---------------------------------------------------------------------------
// QKV GEMM: [8192, 1024] @ [1024, 3072] with direct scatter into g_k/g_q/g_v.
// 64x64 block tile, 4x4 per-thread microtile, K-step 16.
// ---------------------------------------------------------------------------
__global__ __launch_bounds__(256) void qkv_gemm_kernel(
    const float* __restrict__ x, const float* __restrict__ w)
{
    __shared__ float As[16][64];   // [k][row]
    __shared__ float Bs[16][64];   // [k][col]

    const int tid = threadIdx.x;
    const int tx  = tid & 15;      // 0..15 -> 4 cols each
    const int ty  = tid >> 4;      // 0..15 -> 4 rows each
    const int row0 = blockIdx.y * 64;
    const int col0 = blockIdx.x * 64;

    // load indices
    const int ar = tid >> 2;           // 0..63 (row in tile)
    const int ak = (tid & 3) * 4;      // 0,4,8,12 (k in tile)
    const int bk = tid >> 4;           // 0..15 (k in tile)
    const int bc = (tid & 15) * 4;     // 0..60 (col in tile)

    float acc[4][4] = {};

    for (int k0 = 0; k0 < D_; k0 += 16) {
        float4 av = *(const float4*)&x[(size_t)(row0 + ar) * D_ + k0 + ak];
        As[ak + 0][ar] = av.x;
        As[ak + 1][ar] = av.y;
        As[ak + 2][ar] = av.z;
        As[ak + 3][ar] = av.w;
        float4 bv = *(const float4*)&w[(size_t)(k0 + bk) * N3_ + col0 + bc];
        *(float4*)&Bs[bk][bc] = bv;
        __syncthreads();

        #pragma unroll
        for (int kk = 0; kk < 16; kk++) {
            float4 a4 = *(const float4*)&As[kk][ty * 4];
            float4 b4 = *(const float4*)&Bs[kk][tx * 4];
            float a[4] = {a4.x, a4.y, a4.z, a4.w};
            float b[4] = {b4.x, b4.y, b4.z, b4.w};
            #pragma unroll
            for (int i = 0; i < 4; i++)
                #pragma unroll
                for (int j = 0; j < 4; j++)
                    acc[i][j] += a[i] * b[j];
        }
        __syncthreads();
    }

    // Scatter into [B,H,S,hd]. Chunk order in W is (k, q, v).
    // A 64-wide aligned col tile lies entirely within one (part, head).
    const int cbase  = col0 + tx * 4;
    const int part   = cbase >> 10;          // 0=k, 1=q, 2=v
    const int within = cbase & 1023;
    const int h      = within >> 6;
    const int dbase  = within & 63;
    float* dst = (part == 0) ? g_k : (part == 1) ? g_q : g_v;

    #pragma unroll
    for (int i = 0; i < 4; i++) {
        const int r = row0 + ty * 4 + i;
        const int b = r / S_;
        const int s = r - b * S_;
        float* drow = dst + ((size_t)(b * H_ + h) * S_ + s) * HD_ + dbase;
        #pragma unroll
        for (int j = 0; j < 4; j++)
            drow[j] = acc[i][j];
    }
}

// ---------------------------------------------------------------------------
// Flash attention with ALiBi. One block per (b, h, 64-row Q tile).
// 256 threads: thread (ty,tx) owns rows 4ty..4ty+3, cols 4tx..4tx+3.
// ---------------------------------------------------------------------------
#define ROWP 65   // smem row stride (floats) to avoid bank conflicts

__global__ __launch_bounds__(256) void attn_kernel(float* __restrict__ out)
{
    extern __shared__ float sm[];
    float* Qs  = sm;                    // [64][ROWP]  (seq, d)
    float* Ks  = Qs + 64 * ROWP;        // [64][ROWP]  (key, d)
    float* Vs  = Ks + 64 * ROWP;        // [64][ROWP]  (key, d)
    float* Ps  = Vs + 64 * ROWP;        // [64][ROWP]  (qrow, key)
    float* red = Ps + 64 * ROWP;        // [64][16]

    const int tid = threadIdx.x;
    const int tx  = tid & 15;
    const int ty  = tid >> 4;
    const int qt  = blockIdx.x;         // 0..31
    const int h   = blockIdx.y;         // 0..15
    const int b   = blockIdx.z;         // 0..3
    const int bh  = b * H_ + h;
    const int i0  = qt * 64;

    const float slope     = exp2f(-0.5f * (float)(h + 1));  // 1/(2^8)^((h+1)/16)
    const float inv_scale = 1.0f / 32.0f;                    // 1/sqrt(1024)

    const float* qg = g_q + (size_t)bh * S_ * HD_;
    const float* kg = g_k + (size_t)bh * S_ * HD_;
    const float* vg = g_v + (size_t)bh * S_ * HD_;

    // Load Q tile (64 x 64)
    for (int t = tid; t < 64 * 16; t += 256) {
        const int r  = t >> 4;
        const int c4 = (t & 15) * 4;
        float4 v = *(const float4*)&qg[(size_t)(i0 + r) * HD_ + c4];
        Qs[r * ROWP + c4 + 0] = v.x;
        Qs[r * ROWP + c4 + 1] = v.y;
        Qs[r * ROWP + c4 + 2] = v.z;
        Qs[r * ROWP + c4 + 3] = v.w;
    }

    float m_st[4], l_st[4], acc[4][4];
    #pragma unroll
    for (int i = 0; i < 4; i++) {
        m_st[i] = -INFINITY;
        l_st[i] = 0.0f;
        #pragma unroll
        for (int j = 0; j < 4; j++) acc[i][j] = 0.0f;
    }

    for (int kt = 0; kt < S_ / 64; kt++) {
        const int j0 = kt * 64;
        __syncthreads();  // protect Ks/Vs/Ps from previous iteration / Q load done
        for (int t = tid; t < 64 * 16; t += 256) {
            const int r  = t >> 4;
            const int c4 = (t & 15) * 4;
            float4 kv = *(const float4*)&kg[(size_t)(j0 + r) * HD_ + c4];
            Ks[r * ROWP + c4 + 0] = kv.x;
            Ks[r * ROWP + c4 + 1] = kv.y;
            Ks[r * ROWP + c4 + 2] = kv.z;
            Ks[r * ROWP + c4 + 3] = kv.w;
            float4 vv = *(const float4*)&vg[(size_t)(j0 + r) * HD_ + c4];
            Vs[r * ROWP + c4 + 0] = vv.x;
            Vs[r * ROWP + c4 + 1] = vv.y;
            Vs[r * ROWP + c4 + 2] = vv.z;
            Vs[r * ROWP + c4 + 3] = vv.w;
        }
        __syncthreads();

        // Scores: s[i][j] = q_row . k_row
        float s[4][4] = {};
        #pragma unroll 8
        for (int kk = 0; kk < HD_; kk++) {
            float qr[4], kr[4];
            #pragma unroll
            for (int i = 0; i < 4; i++) qr[i] = Qs[(4 * ty + i) * ROWP + kk];
            #pragma unroll
            for (int j = 0; j < 4; j++) kr[j] = Ks[(4 * tx + j) * ROWP + kk];
            #pragma unroll
            for (int i = 0; i < 4; i++)
                #pragma unroll
                for (int j = 0; j < 4; j++)
                    s[i][j] += qr[i] * kr[j];
        }
        // scale + ALiBi bias m_h * (j - i)
        #pragma unroll
        for (int i = 0; i < 4; i++) {
            const float fi = (float)(i0 + 4 * ty + i);
            #pragma unroll
            for (int j = 0; j < 4; j++) {
                const float fj = (float)(j0 + 4 * tx + j);
                s[i][j] = s[i][j] * inv_scale + slope * (fj - fi);
            }
        }

        // Row max reduction
        #pragma unroll
        for (int i = 0; i < 4; i++) {
            float pm = s[i][0];
            #pragma unroll
            for (int j = 1; j < 4; j++) pm = fmaxf(pm, s[i][j]);
            red[(4 * ty + i) * 16 + tx] = pm;
        }
        __syncthreads();
        float mnew[4];
        #pragma unroll
        for (int i = 0; i < 4; i++) {
            float m = m_st[i];
            #pragma unroll
            for (int t = 0; t < 16; t++) m = fmaxf(m, red[(4 * ty + i) * 16 + t]);
            mnew[i] = m;
        }
        __syncthreads();  // red reuse

        // exp, write P, partial row sums
        #pragma unroll
        for (int i = 0; i < 4; i++) {
            float psum = 0.0f;
            #pragma unroll
            for (int j = 0; j < 4; j++) {
                float p = __expf(s[i][j] - mnew[i]);
                Ps[(4 * ty + i) * ROWP + 4 * tx + j] = p;
                psum += p;
            }
            red[(4 * ty + i) * 16 + tx] = psum;
        }
        __syncthreads();

        // Update running stats, rescale accumulators
        #pragma unroll
        for (int i = 0; i < 4; i++) {
            float rs = 0.0f;
            #pragma unroll
            for (int t = 0; t < 16; t++) rs += red[(4 * ty + i) * 16 + t];
            const float alpha = __expf(m_st[i] - mnew[i]);
            l_st[i] = l_st[i] * alpha + rs;
            m_st[i] = mnew[i];
            #pragma unroll
            for (int j = 0; j < 4; j++) acc[i][j] *= alpha;
        }

        // O += P @ V
        #pragma unroll 8
        for (int kk = 0; kk < 64; kk++) {
            float pr[4], vr[4];
            #pragma unroll
            for (int i = 0; i < 4; i++) pr[i] = Ps[(4 * ty + i) * ROWP + kk];
            #pragma unroll
            for (int j = 0; j < 4; j++) vr[j] = Vs[kk * ROWP + 4 * tx + j];
            #pragma unroll
            for (int i = 0; i < 4; i++)
                #pragma unroll
                for (int j = 0; j < 4; j++)
                    acc[i][j] += pr[i] * vr[j];
        }
    }

    // Epilogue: out[b][s][h*64 + d]
    #pragma unroll
    for (int i = 0; i < 4; i++) {
        const int sgl = i0 + 4 * ty + i;
        const float inv_l = 1.0f / l_st[i];
        float* orow = out + ((size_t)b * S_ + sgl) * D_ + h * HD_ + 4 * tx;
        #pragma unroll
        for (int j = 0; j < 4; j++)
            orow[j] = acc[i][j] * inv_l;
    }
}

// ---------------------------------------------------------------------------
extern "C" void kernel_launch(void* const* d_in, const int* in_sizes, int n_in,
                              void* d_out, int out_size)
{
    const float* x = (const float*)d_in[0];      // [4, 2048, 1024]
    const float* w = (const float*)d_in[1];      // [1024, 3072]
    float* out = (float*)d_out;                  // [4, 2048, 1024]

    (void)in_sizes; (void)n_in; (void)out_size;

    // QKV projection
    dim3 gemm_grid(N3_ / 64, (B_ * S_) / 64);    // (48, 128)
    qkv_gemm_kernel<<<gemm_grid, 256>>>(x, w);

    // Attention
    const int smem_bytes = (4 * 64 * ROWP + 64 * 16) * (int)sizeof(float);
    cudaFuncSetAttribute(attn_kernel,
                         cudaFuncAttributeMaxDynamicSharedMemorySize, smem_bytes);
    dim3 attn_grid(S_ / 64, H_, B_);             // (32, 16, 4)
    attn_kernel<<<attn_grid, 256, smem_bytes>>>(out);
}

// round 3
// speedup vs baseline: 1.0002x; 1.0002x over previous
#include <cuda_runtime.h>
#include <math.h>

#define B_   4
#define S_   2048
#define D_   1024
#define H_   16
#define HD_  64
#define N3_  3072   // 3 * D_

// Scratch for projected K, Q, V in [B, H, S, hd] layout (static device
// globals: allocation-free per harness rules). 32 MB each.
__device__ float g_k[(size_t)B_ * H_ * S_ * HD_];
__device__ float g_q[(size_t)B_ * H_ * S_ * HD_];
__device__ float g_v[(size_t)B_ * H_ * S_ * HD_];

// ---------------------------------------------------------------------------
// QKV GEMM: [8192, 1024] @ [1024, 3072] with direct scatter into g_k/g_q/g_v.
// 64x64 block tile, 4x4 per-thread microtile, K-step 16.
// ---------------------------------------------------------------------------
__global__ __launch_bounds__(256) void qkv_gemm_kernel(
    const float* __restrict__ x, const float* __restrict__ w)
{
    __shared__ float As[16][64];   // [k][row]
    __shared__ float Bs[16][64];   // [k][col]

    const int tid = threadIdx.x;
    const int tx  = tid & 15;      // 0..15 -> 4 cols each
    const int ty  = tid >> 4;      // 0..15 -> 4 rows each
    const int row0 = blockIdx.y * 64;
    const int col0 = blockIdx.x * 64;

    // load indices
    const int ar = tid >> 2;           // 0..63 (row in tile)
    const int ak = (tid & 3) * 4;      // 0,4,8,12 (k in tile)
    const int bk = tid >> 4;           // 0..15 (k in tile)
    const int bc = (tid & 15) * 4;     // 0..60 (col in tile)

    float acc[4][4] = {};

    for (int k0 = 0; k0 < D_; k0 += 16) {
        float4 av = *(const float4*)&x[(size_t)(row0 + ar) * D_ + k0 + ak];
        As[ak + 0][ar] = av.x;
        As[ak + 1][ar] = av.y;
        As[ak + 2][ar] = av.z;
        As[ak + 3][ar] = av.w;
        float4 bv = *(const float4*)&w[(size_t)(k0 + bk) * N3_ + col0 + bc];
        *(float4*)&Bs[bk][bc] = bv;
        __syncthreads();

        #pragma unroll
        for (int kk = 0; kk < 16; kk++) {
            float4 a4 = *(const float4*)&As[kk][ty * 4];
            float4 b4 = *(const float4*)&Bs[kk][tx * 4];
            float a[4] = {a4.x, a4.y, a4.z, a4.w};
            float b[4] = {b4.x, b4.y, b4.z, b4.w};
            #pragma unroll
            for (int i = 0; i < 4; i++)
                #pragma unroll
                for (int j = 0; j < 4; j++)
                    acc[i][j] += a[i] * b[j];
        }
        __syncthreads();
    }

    // Scatter into [B,H,S,hd]. Chunk order in W is (k, q, v).
    // A 64-wide aligned col tile lies entirely within one (part, head).
    const int cbase  = col0 + tx * 4;
    const int part   = cbase >> 10;          // 0=k, 1=q, 2=v
    const int within = cbase & 1023;
    const int h      = within >> 6;
    const int dbase  = within & 63;
    float* dst = (part == 0) ? g_k : (part == 1) ? g_q : g_v;

    #pragma unroll
    for (int i = 0; i < 4; i++) {
        const int r = row0 + ty * 4 + i;
        const int b = r / S_;
        const int s = r - b * S_;
        float* drow = dst + ((size_t)(b * H_ + h) * S_ + s) * HD_ + dbase;
        #pragma unroll
        for (int j = 0; j < 4; j++)
            drow[j] = acc[i][j];
    }
}

// ---------------------------------------------------------------------------
// Flash attention with ALiBi. One block per (b, h, 64-row Q tile).
// 256 threads: thread (ty,tx) owns rows 4ty..4ty+3, cols 4tx..4tx+3.
// ---------------------------------------------------------------------------
#define ROWP 65   // smem row stride (floats) to avoid bank conflicts

__global__ __launch_bounds__(256) void attn_kernel(float* __restrict__ out)
{
    extern __shared__ float sm[];
    float* Qs  = sm;                    // [64][ROWP]  (seq, d)
    float* Ks  = Qs + 64 * ROWP;        // [64][ROWP]  (key, d)
    float* Vs  = Ks + 64 * ROWP;        // [64][ROWP]  (key, d)
    float* Ps  = Vs + 64 * ROWP;        // [64][ROWP]  (qrow, key)
    float* red = Ps + 64 * ROWP;        // [64][16]

    const int tid = threadIdx.x;
    const int tx  = tid & 15;
    const int ty  = tid >> 4;
    const int qt  = blockIdx.x;         // 0..31
    const int h   = blockIdx.y;         // 0..15
    const int b   = blockIdx.z;         // 0..3
    const int bh  = b * H_ + h;
    const int i0  = qt * 64;

    const float slope     = exp2f(-0.5f * (float)(h + 1));  // 1/(2^8)^((h+1)/16)
    const float inv_scale = 1.0f / 32.0f;                    // 1/sqrt(1024)

    const float* qg = g_q + (size_t)bh * S_ * HD_;
    const float* kg = g_k + (size_t)bh * S_ * HD_;
    const float* vg = g_v + (size_t)bh * S_ * HD_;

    // Load Q tile (64 x 64)
    for (int t = tid; t < 64 * 16; t += 256) {
        const int r  = t >> 4;
        const int c4 = (t & 15) * 4;
        float4 v = *(const float4*)&qg[(size_t)(i0 + r) * HD_ + c4];
        Qs[r * ROWP + c4 + 0] = v.x;
        Qs[r * ROWP + c4 + 1] = v.y;
        Qs[r * ROWP + c4 + 2] = v.z;
        Qs[r * ROWP + c4 + 3] = v.w;
    }

    float m_st[4], l_st[4], acc[4][4];
    #pragma unroll
    for (int i = 0; i < 4; i++) {
        m_st[i] = -INFINITY;
        l_st[i] = 0.0f;
        #pragma unroll
        for (int j = 0; j < 4; j++) acc[i][j] = 0.0f;
    }

    for (int kt = 0; kt < S_ / 64; kt++) {
        const int j0 = kt * 64;
        __syncthreads();  // protect Ks/Vs/Ps from previous iteration / Q load done
        for (int t = tid; t < 64 * 16; t += 256) {
            const int r  = t >> 4;
            const int c4 = (t & 15) * 4;
            float4 kv = *(const float4*)&kg[(size_t)(j0 + r) * HD_ + c4];
            Ks[r * ROWP + c4 + 0] = kv.x;
            Ks[r * ROWP + c4 + 1] = kv.y;
            Ks[r * ROWP + c4 + 2] = kv.z;
            Ks[r * ROWP + c4 + 3] = kv.w;
            float4 vv = *(const float4*)&vg[(size_t)(j0 + r) * HD_ + c4];
            Vs[r * ROWP + c4 + 0] = vv.x;
            Vs[r * ROWP + c4 + 1] = vv.y;
            Vs[r * ROWP + c4 + 2] = vv.z;
            Vs[r * ROWP + c4 + 3] = vv.w;
        }
        __syncthreads();

        // Scores: s[i][j] = q_row . k_row
        float s[4][4] = {};
        #pragma unroll 8
        for (int kk = 0; kk < HD_; kk++) {
            float qr[4], kr[4];
            #pragma unroll
            for (int i = 0; i < 4; i++) qr[i] = Qs[(4 * ty + i) * ROWP + kk];
            #pragma unroll
            for (int j = 0; j < 4; j++) kr[j] = Ks[(4 * tx + j) * ROWP + kk];
            #pragma unroll
            for (int i = 0; i < 4; i++)
                #pragma unroll
                for (int j = 0; j < 4; j++)
                    s[i][j] += qr[i] * kr[j];
        }
        // scale + ALiBi bias m_h * (j - i)
        #pragma unroll
        for (int i = 0; i < 4; i++) {
            const float fi = (float)(i0 + 4 * ty + i);
            #pragma unroll
            for (int j = 0; j < 4; j++) {
                const float fj = (float)(j0 + 4 * tx + j);
                s[i][j] = s[i][j] * inv_scale + slope * (fj - fi);
            }
        }

        // Row max reduction
        #pragma unroll
        for (int i = 0; i < 4; i++) {
            float pm = s[i][0];
            #pragma unroll
            for (int j = 1; j < 4; j++) pm = fmaxf(pm, s[i][j]);
            red[(4 * ty + i) * 16 + tx] = pm;
        }
        __syncthreads();
        float mnew[4];
        #pragma unroll
        for (int i = 0; i < 4; i++) {
            float m = m_st[i];
            #pragma unroll
            for (int t = 0; t < 16; t++) m = fmaxf(m, red[(4 * ty + i) * 16 + t]);
            mnew[i] = m;
        }
        __syncthreads();  // red reuse

        // exp, write P, partial row sums
        #pragma unroll
        for (int i = 0; i < 4; i++) {
            float psum = 0.0f;
            #pragma unroll
            for (int j = 0; j < 4; j++) {
                float p = __expf(s[i][j] - mnew[i]);
                Ps[(4 * ty + i) * ROWP + 4 * tx + j] = p;
                psum += p;
            }
            red[(4 * ty + i) * 16 + tx] = psum;
        }
        __syncthreads();

        // Update running stats, rescale accumulators
        #pragma unroll
        for (int i = 0; i < 4; i++) {
            float rs = 0.0f;
            #pragma unroll
            for (int t = 0; t < 16; t++) rs += red[(4 * ty + i) * 16 + t];
            const float alpha = __expf(m_st[i] - mnew[i]);
            l_st[i] = l_st[i] * alpha + rs;
            m_st[i] = mnew[i];
            #pragma unroll
            for (int j = 0; j < 4; j++) acc[i][j] *= alpha;
        }

        // O += P @ V
        #pragma unroll 8
        for (int kk = 0; kk < 64; kk++) {
            float pr[4], vr[4];
            #pragma unroll
            for (int i = 0; i < 4; i++) pr[i] = Ps[(4 * ty + i) * ROWP + kk];
            #pragma unroll
            for (int j = 0; j < 4; j++) vr[j] = Vs[kk * ROWP + 4 * tx + j];
            #pragma unroll
            for (int i = 0; i < 4; i++)
                #pragma unroll
                for (int j = 0; j < 4; j++)
                    acc[i][j] += pr[i] * vr[j];
        }
    }

    // Epilogue: out[b][s][h*64 + d]
    #pragma unroll
    for (int i = 0; i < 4; i++) {
        const int sgl = i0 + 4 * ty + i;
        const float inv_l = 1.0f / l_st[i];
        float* orow = out + ((size_t)b * S_ + sgl) * D_ + h * HD_ + 4 * tx;
        #pragma unroll
        for (int j = 0; j < 4; j++)
            orow[j] = acc[i][j] * inv_l;
    }
}

// ---------------------------------------------------------------------------
extern "C" void kernel_launch(void* const* d_in, const int* in_sizes, int n_in,
                              void* d_out, int out_size)
{
    const float* x = (const float*)d_in[0];      // [4, 2048, 1024]
    const float* w = (const float*)d_in[1];      // [1024, 3072]
    float* out = (float*)d_out;                  // [4, 2048, 1024]

    (void)in_sizes; (void)n_in; (void)out_size;

    // QKV projection
    dim3 gemm_grid(N3_ / 64, (B_ * S_) / 64);    // (48, 128)
    qkv_gemm_kernel<<<gemm_grid, 256>>>(x, w);

    // Attention
    const int smem_bytes = (4 * 64 * ROWP + 64 * 16) * (int)sizeof(float);
    cudaFuncSetAttribute(attn_kernel,
                         cudaFuncAttributeMaxDynamicSharedMemorySize, smem_bytes);
    dim3 attn_grid(S_ / 64, H_, B_);             // (32, 16, 4)
    attn_kernel<<<attn_grid, 256, smem_bytes>>>(out);
}

// round 6
// speedup vs baseline: 4.2216x; 4.2209x over previous
#include <cuda_runtime.h>
#include <cuda_fp16.h>
#include <math.h>

#define QF_ 0.04508422002777998f   // log2(e)/32

// ------------------------- device scratch (no allocs) ----------------------
__device__ __half g_Xh[(size_t)8192*1024];
__device__ __half g_Xl[(size_t)8192*1024];
__device__ __half g_Wh[(size_t)3072*1024];   // W^T [n][k]
__device__ __half g_Wl[(size_t)3072*1024];
__device__ __half g_Qh[(size_t)64*2048*64];  // [bh][s][d] (pre-scaled by QF)
__device__ __half g_Ql[(size_t)64*2048*64];
__device__ __half g_Kh[(size_t)64*2048*64];
__device__ __half g_Kl[(size_t)64*2048*64];
__device__ __half g_Vth[(size_t)64*2048*64]; // [bh][s][d] temp
__device__ __half g_Vtl[(size_t)64*2048*64];
__device__ __half g_Vh[(size_t)64*64*2048];  // [bh][d][s]
__device__ __half g_Vl[(size_t)64*64*2048];

// ------------------------------ helpers ------------------------------------
__device__ __forceinline__ unsigned su32(const void* p){
    unsigned a;
    asm("{ .reg .u64 t; cvta.to.shared.u64 t, %1; cvt.u32.u64 %0, t; }":"=r"(a):"l"(p));
    return a;
}
#define SWZ(o) ((unsigned)(o) ^ ((((unsigned)(o)) >> 3) & 0x70))

__device__ __forceinline__ void ldsm4(unsigned* r, unsigned a){
    asm volatile("ldmatrix.sync.aligned.m8n8.x4.shared.b16 {%0,%1,%2,%3}, [%4];"
                 : "=r"(r[0]),"=r"(r[1]),"=r"(r[2]),"=r"(r[3]) : "r"(a));
}
__device__ __forceinline__ void mma16816(float* d, const unsigned* a, unsigned b0, unsigned b1){
    asm volatile("mma.sync.aligned.m16n8k16.row.col.f32.f16.f16.f32 "
                 "{%0,%1,%2,%3},{%4,%5,%6,%7},{%8,%9},{%0,%1,%2,%3};"
                 : "+f"(d[0]),"+f"(d[1]),"+f"(d[2]),"+f"(d[3])
                 : "r"(a[0]),"r"(a[1]),"r"(a[2]),"r"(a[3]),"r"(b0),"r"(b1));
}
__device__ __forceinline__ float ex2f(float x){
    float r; asm("ex2.approx.ftz.f32 %0, %1;":"=f"(r):"f"(x)); return r;
}
__device__ __forceinline__ unsigned packh(float a, float b){
    __half2 h = __floats2half2_rn(a, b);
    return *(unsigned*)&h;
}
__device__ __forceinline__ unsigned packhh(__half a, __half b){
    __half2 h = __halves2half2(a, b);
    return *(unsigned*)&h;
}
__device__ __forceinline__ void split8h(const float* v, uint4* H, uint4* L){
    unsigned hw[4], lw[4];
    #pragma unroll
    for(int k=0;k<4;k++){
        __half h0 = __float2half_rn(v[2*k]);
        __half h1 = __float2half_rn(v[2*k+1]);
        hw[k] = packhh(h0, h1);
        lw[k] = packh(v[2*k] - __half2float(h0), v[2*k+1] - __half2float(h1));
    }
    *H = make_uint4(hw[0],hw[1],hw[2],hw[3]);
    *L = make_uint4(lw[0],lw[1],lw[2],lw[3]);
}

// ---------------------------- split X ---------------------------------------
__global__ __launch_bounds__(256) void splitx_kernel(const float* __restrict__ x){
    size_t i = ((size_t)blockIdx.x * 256 + threadIdx.x) * 8;
    float v[8];
    *(float4*)(v)   = *(const float4*)(x + i);
    *(float4*)(v+4) = *(const float4*)(x + i + 4);
    uint4 H, L;
    split8h(v, &H, &L);
    *(uint4*)(g_Xh + i) = H;
    *(uint4*)(g_Xl + i) = L;
}

// ------------------------ split + transpose W -------------------------------
__global__ __launch_bounds__(256) void splitw_kernel(const float* __restrict__ w){
    __shared__ float ws[64][65];
    const int n0 = blockIdx.x * 64, k0 = blockIdx.y * 64;
    #pragma unroll
    for(int i=0;i<4;i++){
        int e = i*256 + threadIdx.x;
        int r = e >> 4, c4 = (e & 15) * 4;
        float4 t = *(const float4*)(w + (size_t)(k0 + r) * 3072 + n0 + c4);
        ws[r][c4+0]=t.x; ws[r][c4+1]=t.y; ws[r][c4+2]=t.z; ws[r][c4+3]=t.w;
    }
    __syncthreads();
    int n = threadIdx.x >> 2, sg = (threadIdx.x & 3) * 16;
    float v[16];
    #pragma unroll
    for(int j=0;j<16;j++) v[j] = ws[sg + j][n];
    uint4 H0,L0,H1,L1;
    split8h(v, &H0, &L0); split8h(v+8, &H1, &L1);
    __half* dh = g_Wh + (size_t)(n0 + n) * 1024 + k0 + sg;
    __half* dl = g_Wl + (size_t)(n0 + n) * 1024 + k0 + sg;
    *(uint4*)(dh) = H0; *(uint4*)(dh + 8) = H1;
    *(uint4*)(dl) = L0; *(uint4*)(dl + 8) = L1;
}

// ------------------------------ QKV GEMM ------------------------------------
// grid (24, 64), 256 thr. smem: AH 0, AL 16K, BH 32K, BL 48K (SW128 tiles).
// Epilogue staging: hi [128][136] half @0, lo @34816. GSM=69632.
#define GSM 69632

__global__ __launch_bounds__(256,2) void gemm_kernel(){
    extern __shared__ char sm[];
    const unsigned sb = su32(sm);
    const int tid = threadIdx.x, lane = tid & 31, wid = tid >> 5;
    const int wr = wid & 3, wc = wid >> 2;
    const int m0 = blockIdx.y * 128, n0 = blockIdx.x * 128;

    float acc[2][8][4];
    #pragma unroll
    for(int a=0;a<2;a++)
        #pragma unroll
        for(int b=0;b<8;b++)
            #pragma unroll
            for(int c=0;c<4;c++) acc[a][b][c]=0.0f;

    const int rr  = (lane & 7) + ((lane >> 3) & 1) * 8;
    const int csl = lane >> 4;

    for(int c = 0; c < 16; c++){
        const int k0 = c * 64;
        __syncthreads();
        #pragma unroll
        for(int j = 0; j < 4; j++){
            int i = tid + j*256;
            int r = i >> 3, ch = i & 7;
            unsigned o = SWZ(r*128 + ch*16);
            size_t ga = (size_t)(m0 + r) * 1024 + k0 + ch*8;
            size_t gb = (size_t)(n0 + r) * 1024 + k0 + ch*8;
            *(uint4*)(sm + o)         = *(const uint4*)(g_Xh + ga);
            *(uint4*)(sm + 16384 + o) = *(const uint4*)(g_Xl + ga);
            *(uint4*)(sm + 32768 + o) = *(const uint4*)(g_Wh + gb);
            *(uint4*)(sm + 49152 + o) = *(const uint4*)(g_Wl + gb);
        }
        __syncthreads();

        #pragma unroll
        for(int ks = 0; ks < 4; ks++){
            unsigned ah[2][4], al[2][4];
            const int cc2 = ks*2 + csl;
            #pragma unroll
            for(int mt = 0; mt < 2; mt++){
                unsigned ra = sb + SWZ((wr*32 + mt*16 + rr)*128 + cc2*16);
                ldsm4(ah[mt], ra);
                ldsm4(al[mt], ra + 16384);
            }
            #pragma unroll
            for(int hf = 0; hf < 2; hf++){
                unsigned bh[2][4], bl[2][4];
                #pragma unroll
                for(int g = 0; g < 2; g++){
                    unsigned rb = sb + 32768 + SWZ((wc*64 + hf*32 + g*16 + rr)*128 + cc2*16);
                    ldsm4(bh[g], rb);
                    ldsm4(bl[g], rb + 16384);
                }
                #pragma unroll
                for(int g = 0; g < 2; g++)
                    #pragma unroll
                    for(int sub = 0; sub < 2; sub++){
                        const int nt = hf*4 + g*2 + sub;
                        #pragma unroll
                        for(int mt = 0; mt < 2; mt++){
                            mma16816(acc[mt][nt], ah[mt], bh[g][sub], bh[g][sub+2]);
                            mma16816(acc[mt][nt], al[mt], bh[g][sub], bh[g][sub+2]);
                            mma16816(acc[mt][nt], ah[mt], bl[g][sub], bl[g][sub+2]);
                        }
                    }
            }
        }
    }
    __syncthreads();

    // Stage fp16 hi/lo into smem, then coalesced global writes.
    const int part = n0 >> 10;          // 0=K, 1=Q, 2=V
    const int h0   = (n0 & 1023) >> 6;
    const float sc = (part == 1) ? QF_ : 1.0f;
    __half *gh, *gl;
    if(part == 0){ gh = g_Kh;  gl = g_Kl;  }
    else if(part == 1){ gh = g_Qh; gl = g_Ql; }
    else { gh = g_Vth; gl = g_Vtl; }

    #pragma unroll
    for(int mt = 0; mt < 2; mt++)
        #pragma unroll
        for(int nt = 0; nt < 8; nt++){
            const int r0 = wr*32 + mt*16 + (lane >> 2);
            const int cc = wc*64 + nt*8 + (lane & 3)*2;
            float v0 = acc[mt][nt][0]*sc, v1 = acc[mt][nt][1]*sc;
            float v2 = acc[mt][nt][2]*sc, v3 = acc[mt][nt][3]*sc;
            __half h0a = __float2half_rn(v0), h1a = __float2half_rn(v1);
            __half h2a = __float2half_rn(v2), h3a = __float2half_rn(v3);
            *(unsigned*)(sm + r0*272 + cc*2)             = packhh(h0a, h1a);
            *(unsigned*)(sm + (r0+8)*272 + cc*2)         = packhh(h2a, h3a);
            *(unsigned*)(sm + 34816 + r0*272 + cc*2)     = packh(v0-__half2float(h0a), v1-__half2float(h1a));
            *(unsigned*)(sm + 34816 + (r0+8)*272 + cc*2) = packh(v2-__half2float(h2a), v3-__half2float(h3a));
        }
    __syncthreads();

    #pragma unroll
    for(int j = 0; j < 8; j++){
        int i = tid + j*256;
        int r = i >> 4, cc = i & 15;
        int gr = m0 + r;
        int b = gr >> 11, s = gr & 2047;
        int h = h0 + (cc >> 3);
        size_t off = (((size_t)(b*16 + h)*2048 + s)*64) + (size_t)(cc & 7)*8;
        *(uint4*)(gh + off) = *(uint4*)(sm + r*272 + cc*16);
        *(uint4*)(gl + off) = *(uint4*)(sm + 34816 + r*272 + cc*16);
    }
}

// ---------------------------- transpose V -----------------------------------
__global__ __launch_bounds__(256) void transv_kernel(){
    __shared__ __half th[64][72], tl[64][72];
    const int s0 = blockIdx.x * 64, bh = blockIdx.y;
    const size_t ib = (size_t)bh * 131072;
    #pragma unroll
    for(int i = 0; i < 2; i++){
        int e = i*256 + threadIdx.x;
        int r = e >> 3, g = e & 7;
        *(uint4*)&th[r][g*8] = *(const uint4*)(g_Vth + ib + (size_t)(s0 + r)*64 + g*8);
        *(uint4*)&tl[r][g*8] = *(const uint4*)(g_Vtl + ib + (size_t)(s0 + r)*64 + g*8);
    }
    __syncthreads();
    const int d = threadIdx.x >> 2, sg = (threadIdx.x & 3) * 16;
    unsigned uh[4], ul[4];
    #pragma unroll
    for(int half8 = 0; half8 < 2; half8++){
        #pragma unroll
        for(int j = 0; j < 4; j++){
            int jj = half8*4 + j;
            uh[j] = packhh(th[sg+2*jj][d], th[sg+2*jj+1][d]);
            ul[j] = packhh(tl[sg+2*jj][d], tl[sg+2*jj+1][d]);
        }
        __half* oh = g_Vh + ib + (size_t)d * 2048 + s0 + sg + half8*8;
        __half* ol = g_Vl + ib + (size_t)d * 2048 + s0 + sg + half8*8;
        *(uint4*)oh = *(uint4*)uh;
        *(uint4*)ol = *(uint4*)ul;
    }
}

// ------------------------------ attention -----------------------------------
// grid (16, 64): (qtile, bh). 256 thr (8 warps, 16 q-rows each).
// smem: QH 0 (16K), QL 16K, KH 32K (8K), KL 40K, VH 48K, VL 56K. ASM=65536.
#define ASM 65536

__global__ __launch_bounds__(256) void attn_kernel(float* __restrict__ out){
    extern __shared__ char sm[];
    const unsigned sb = su32(sm);
    const int tid = threadIdx.x, lane = tid & 31, w = tid >> 5;
    const int qt = blockIdx.x, bh = blockIdx.y;
    const int h = bh & 15, b = bh >> 4;
    const int i0 = qt * 128;
    const size_t ib = (size_t)bh * 131072;

    const float slope = exp2f(-0.5f * (float)(h + 1));
    const float c2 = slope * 1.4426950408889634f;

    // load Q tile (swizzled)
    #pragma unroll
    for(int j = 0; j < 4; j++){
        int i = tid + j*256;
        int r = i >> 3, ch = i & 7;
        unsigned o = SWZ(r*128 + ch*16);
        size_t ga = ib + (size_t)(i0 + r)*64 + ch*8;
        *(uint4*)(sm + o)         = *(const uint4*)(g_Qh + ga);
        *(uint4*)(sm + 16384 + o) = *(const uint4*)(g_Ql + ga);
    }
    __syncthreads();

    const int rr  = (lane & 7) + ((lane >> 3) & 1) * 8;
    const int csl = lane >> 4;

    unsigned qh[4][4], ql[4][4];
    #pragma unroll
    for(int ks = 0; ks < 4; ks++){
        unsigned ra = sb + SWZ((w*16 + rr)*128 + (ks*2 + csl)*16);
        ldsm4(qh[ks], ra);
        ldsm4(ql[ks], ra + 16384);
    }

    float o_[8][4];
    #pragma unroll
    for(int a=0;a<8;a++)
        #pragma unroll
        for(int e=0;e<4;e++) o_[a][e]=0.0f;
    float l0 = 0.0f, l1 = 0.0f;

    int kt0 = 0;
    while(kt0 < 31 && c2 * (float)(1984 - 64*kt0) > 43.0f) kt0++;

    for(int kt = kt0; kt < 32; kt++){
        const int j0 = kt * 64;
        __syncthreads();
        #pragma unroll
        for(int j = 0; j < 2; j++){
            int i = tid + j*256;
            int r = i >> 3, ch = i & 7;
            unsigned o = SWZ(r*128 + ch*16);
            size_t gk = ib + (size_t)(j0 + r)*64 + ch*8;
            size_t gv = ib + (size_t)r*2048 + j0 + ch*8;
            *(uint4*)(sm + 32768 + o) = *(const uint4*)(g_Kh + gk);
            *(uint4*)(sm + 40960 + o) = *(const uint4*)(g_Kl + gk);
            *(uint4*)(sm + 49152 + o) = *(const uint4*)(g_Vh + gv);
            *(uint4*)(sm + 57344 + o) = *(const uint4*)(g_Vl + gv);
        }
        __syncthreads();

        // S = Q @ K^T  (3-split)
        float s_[8][4];
        #pragma unroll
        for(int a=0;a<8;a++)
            #pragma unroll
            for(int e=0;e<4;e++) s_[a][e]=0.0f;
        #pragma unroll
        for(int ks = 0; ks < 4; ks++){
            unsigned kbh[4][4], kbl[4][4];
            #pragma unroll
            for(int g = 0; g < 4; g++){
                unsigned rb = sb + 32768 + SWZ((g*16 + rr)*128 + (ks*2 + csl)*16);
                ldsm4(kbh[g], rb);
                ldsm4(kbl[g], rb + 8192);
            }
            #pragma unroll
            for(int g = 0; g < 4; g++)
                #pragma unroll
                for(int sub = 0; sub < 2; sub++){
                    const int nt = g*2 + sub;
                    mma16816(s_[nt], qh[ks], kbh[g][sub], kbh[g][sub+2]);
                    mma16816(s_[nt], ql[ks], kbh[g][sub], kbh[g][sub+2]);
                    mma16816(s_[nt], qh[ks], kbl[g][sub], kbl[g][sub+2]);
                }
        }

        // exp2 with analytic shift; build P fragments (hi/lo fp16)
        unsigned ph[4][4], pl[4][4];
        #pragma unroll
        for(int nt = 0; nt < 8; nt++){
            const float jb = (float)(j0 + nt*8 + (lane & 3)*2 - 2047);
            float p0 = ex2f(fmaf(c2, jb,        s_[nt][0]));
            float p1 = ex2f(fmaf(c2, jb + 1.0f, s_[nt][1]));
            float p2 = ex2f(fmaf(c2, jb,        s_[nt][2]));
            float p3 = ex2f(fmaf(c2, jb + 1.0f, s_[nt][3]));
            l0 += p0 + p1;
            l1 += p2 + p3;
            __half h0a = __float2half_rn(p0), h1a = __float2half_rn(p1);
            __half h2a = __float2half_rn(p2), h3a = __float2half_rn(p3);
            const int kk = nt >> 1, od = nt & 1;
            ph[kk][od ? 2 : 0] = packhh(h0a, h1a);
            ph[kk][od ? 3 : 1] = packhh(h2a, h3a);
            pl[kk][od ? 2 : 0] = packh(p0-__half2float(h0a), p1-__half2float(h1a));
            pl[kk][od ? 3 : 1] = packh(p2-__half2float(h2a), p3-__half2float(h3a));
        }

        // O += P @ V  (V stored [d][s]; 3-split)
        #pragma unroll
        for(int kk = 0; kk < 4; kk++){
            unsigned vbh[4][4], vbl[4][4];
            #pragma unroll
            for(int g = 0; g < 4; g++){
                unsigned rb = sb + 49152 + SWZ((g*16 + rr)*128 + (kk*2 + csl)*16);
                ldsm4(vbh[g], rb);
                ldsm4(vbl[g], rb + 8192);
            }
            #pragma unroll
            for(int g = 0; g < 4; g++)
                #pragma unroll
                for(int sub = 0; sub < 2; sub++){
                    const int nt = g*2 + sub;
                    mma16816(o_[nt], ph[kk], vbh[g][sub], vbh[g][sub+2]);
                    mma16816(o_[nt], pl[kk], vbh[g][sub], vbh[g][sub+2]);
                    mma16816(o_[nt], ph[kk], vbl[g][sub], vbl[g][sub+2]);
                }
        }
    }

    // reduce l within quads
    l0 += __shfl_xor_sync(0xffffffffu, l0, 1);
    l0 += __shfl_xor_sync(0xffffffffu, l0, 2);
    l1 += __shfl_xor_sync(0xffffffffu, l1, 1);
    l1 += __shfl_xor_sync(0xffffffffu, l1, 2);
    const float inv0 = 1.0f / l0, inv1 = 1.0f / l1;

    const int r0g = i0 + w*16 + (lane >> 2);
    float* op0 = out + ((size_t)b*2048 + r0g)*1024 + h*64 + (lane & 3)*2;
    float* op1 = out + ((size_t)b*2048 + r0g + 8)*1024 + h*64 + (lane & 3)*2;
    #pragma unroll
    for(int nt = 0; nt < 8; nt++){
        *(float2*)(op0 + nt*8) = make_float2(o_[nt][0]*inv0, o_[nt][1]*inv0);
        *(float2*)(op1 + nt*8) = make_float2(o_[nt][2]*inv1, o_[nt][3]*inv1);
    }
}

// ------------------------------- launch --------------------------------------
extern "C" void kernel_launch(void* const* d_in, const int* in_sizes, int n_in,
                              void* d_out, int out_size)
{
    const float* x = (const float*)d_in[0];
    const float* w = (const float*)d_in[1];
    float* out = (float*)d_out;
    (void)in_sizes; (void)n_in; (void)out_size;

    splitx_kernel<<<4096, 256>>>(x);
    splitw_kernel<<<dim3(48, 16), 256>>>(w);

    cudaFuncSetAttribute(gemm_kernel, cudaFuncAttributeMaxDynamicSharedMemorySize, GSM);
    gemm_kernel<<<dim3(24, 64), 256, GSM>>>();

    transv_kernel<<<dim3(32, 64), 256>>>();

    cudaFuncSetAttribute(attn_kernel, cudaFuncAttributeMaxDynamicSharedMemorySize, ASM);
    attn_kernel<<<dim3(16, 64), 256, ASM>>>(out);
}

// round 7
// speedup vs baseline: 6.5061x; 1.5411x over previous
#include <cuda_runtime.h>
#include <cuda_fp16.h>
#include <math.h>

#define QF_ 0.04508422002777998f   // log2(e)/32

// ------------------------- device scratch (no allocs) ----------------------
__device__ __half g_Xh[(size_t)8192*1024];
__device__ __half g_Wh[(size_t)3072*1024];   // W^T [n][k]
__device__ __half g_Wl[(size_t)3072*1024];
__device__ __half g_Qh[(size_t)64*2048*64];  // [bh][s][d] (pre-scaled by QF)
__device__ __half g_Kh[(size_t)64*2048*64];
__device__ __half g_Kl[(size_t)64*2048*64];
__device__ __half g_Vth[(size_t)64*2048*64]; // [bh][s][d] temp
__device__ __half g_Vtl[(size_t)64*2048*64];
__device__ __half g_Vh[(size_t)64*64*2048];  // [bh][d][s]
__device__ __half g_Vl[(size_t)64*64*2048];

// ------------------------------ helpers ------------------------------------
__device__ __forceinline__ unsigned su32(const void* p){
    unsigned a;
    asm("{ .reg .u64 t; cvta.to.shared.u64 t, %1; cvt.u32.u64 %0, t; }":"=r"(a):"l"(p));
    return a;
}
#define SWZ(o) ((unsigned)(o) ^ ((((unsigned)(o)) >> 3) & 0x70))

__device__ __forceinline__ void cpa16(unsigned dst, const void* src){
    asm volatile("cp.async.cg.shared.global [%0], [%1], 16;"::"r"(dst),"l"(src));
}
#define CP_COMMIT() asm volatile("cp.async.commit_group;" ::: "memory")
#define CP_WAIT1()  asm volatile("cp.async.wait_group 1;" ::: "memory")
#define CP_WAIT0()  asm volatile("cp.async.wait_group 0;" ::: "memory")

__device__ __forceinline__ void ldsm4(unsigned* r, unsigned a){
    asm volatile("ldmatrix.sync.aligned.m8n8.x4.shared.b16 {%0,%1,%2,%3}, [%4];"
                 : "=r"(r[0]),"=r"(r[1]),"=r"(r[2]),"=r"(r[3]) : "r"(a));
}
__device__ __forceinline__ void mma16816(float* d, const unsigned* a, unsigned b0, unsigned b1){
    asm volatile("mma.sync.aligned.m16n8k16.row.col.f32.f16.f16.f32 "
                 "{%0,%1,%2,%3},{%4,%5,%6,%7},{%8,%9},{%0,%1,%2,%3};"
                 : "+f"(d[0]),"+f"(d[1]),"+f"(d[2]),"+f"(d[3])
                 : "r"(a[0]),"r"(a[1]),"r"(a[2]),"r"(a[3]),"r"(b0),"r"(b1));
}
__device__ __forceinline__ float ex2f(float x){
    float r; asm("ex2.approx.ftz.f32 %0, %1;":"=f"(r):"f"(x)); return r;
}
__device__ __forceinline__ unsigned packh(float a, float b){
    __half2 h = __floats2half2_rn(a, b);
    return *(unsigned*)&h;
}
__device__ __forceinline__ unsigned packhh(__half a, __half b){
    __half2 h = __halves2half2(a, b);
    return *(unsigned*)&h;
}
__device__ __forceinline__ void split8h(const float* v, uint4* H, uint4* L){
    unsigned hw[4], lw[4];
    #pragma unroll
    for(int k=0;k<4;k++){
        __half h0 = __float2half_rn(v[2*k]);
        __half h1 = __float2half_rn(v[2*k+1]);
        hw[k] = packhh(h0, h1);
        lw[k] = packh(v[2*k] - __half2float(h0), v[2*k+1] - __half2float(h1));
    }
    *H = make_uint4(hw[0],hw[1],hw[2],hw[3]);
    *L = make_uint4(lw[0],lw[1],lw[2],lw[3]);
}

// ---------------------------- split X (hi only) ------------------------------
__global__ __launch_bounds__(256) void splitx_kernel(const float* __restrict__ x){
    size_t i = ((size_t)blockIdx.x * 256 + threadIdx.x) * 8;
    float4 a = *(const float4*)(x + i);
    float4 b = *(const float4*)(x + i + 4);
    uint4 H;
    H.x = packh(a.x, a.y); H.y = packh(a.z, a.w);
    H.z = packh(b.x, b.y); H.w = packh(b.z, b.w);
    *(uint4*)(g_Xh + i) = H;
}

// ------------------------ split + transpose W -------------------------------
__global__ __launch_bounds__(256) void splitw_kernel(const float* __restrict__ w){
    __shared__ float ws[64][65];
    const int n0 = blockIdx.x * 64, k0 = blockIdx.y * 64;
    #pragma unroll
    for(int i=0;i<4;i++){
        int e = i*256 + threadIdx.x;
        int r = e >> 4, c4 = (e & 15) * 4;
        float4 t = *(const float4*)(w + (size_t)(k0 + r) * 3072 + n0 + c4);
        ws[r][c4+0]=t.x; ws[r][c4+1]=t.y; ws[r][c4+2]=t.z; ws[r][c4+3]=t.w;
    }
    __syncthreads();
    int n = threadIdx.x >> 2, sg = (threadIdx.x & 3) * 16;
    float v[16];
    #pragma unroll
    for(int j=0;j<16;j++) v[j] = ws[sg + j][n];
    uint4 H0,L0,H1,L1;
    split8h(v, &H0, &L0); split8h(v+8, &H1, &L1);
    __half* dh = g_Wh + (size_t)(n0 + n) * 1024 + k0 + sg;
    __half* dl = g_Wl + (size_t)(n0 + n) * 1024 + k0 + sg;
    *(uint4*)(dh) = H0; *(uint4*)(dh + 8) = H1;
    *(uint4*)(dl) = L0; *(uint4*)(dl + 8) = L1;
}

// ------------------------------ QKV GEMM ------------------------------------
// grid (24, 64), 256 thr. Double-buffered cp.async pipeline.
// Stage s (49152 B each): AH +0 (16K), BH +16K, BL +32K. GSM=98304.
#define GSM 98304

__global__ __launch_bounds__(256) void gemm_kernel(){
    extern __shared__ char sm[];
    const unsigned sb = su32(sm);
    const int tid = threadIdx.x, lane = tid & 31, wid = tid >> 5;
    const int wr = wid & 3, wc = wid >> 2;
    const int m0 = blockIdx.y * 128, n0 = blockIdx.x * 128;

    float acc[2][8][4];
    #pragma unroll
    for(int a=0;a<2;a++)
        #pragma unroll
        for(int b=0;b<8;b++)
            #pragma unroll
            for(int c=0;c<4;c++) acc[a][b][c]=0.0f;

    const int rr  = (lane & 7) + ((lane >> 3) & 1) * 8;
    const int csl = lane >> 4;

    // load-issue index (constant across stages)
    const int lr = tid >> 3, lch = tid & 7;
    const unsigned lo_sw[4] = { SWZ((lr     )*128 + lch*16), SWZ((lr + 32)*128 + lch*16),
                                SWZ((lr + 64)*128 + lch*16), SWZ((lr + 96)*128 + lch*16) };

    #define G_ISSUE(c, st) do{ \
        const int k0_ = (c) * 64; \
        const unsigned base_ = sb + (st) * 49152; \
        _Pragma("unroll") \
        for(int j_ = 0; j_ < 4; j_++){ \
            int r_ = lr + j_*32; \
            unsigned o_ = lo_sw[j_]; \
            cpa16(base_ + o_,         g_Xh + (size_t)(m0 + r_) * 1024 + k0_ + lch*8); \
            cpa16(base_ + 16384 + o_, g_Wh + (size_t)(n0 + r_) * 1024 + k0_ + lch*8); \
            cpa16(base_ + 32768 + o_, g_Wl + (size_t)(n0 + r_) * 1024 + k0_ + lch*8); \
        } \
        CP_COMMIT(); \
    }while(0)

    G_ISSUE(0, 0);

    for(int c = 0; c < 16; c++){
        if(c < 15){ G_ISSUE(c + 1, (c + 1) & 1); CP_WAIT1(); }
        else      { CP_WAIT0(); }
        __syncthreads();
        const unsigned base = sb + (c & 1) * 49152;

        #pragma unroll
        for(int ks = 0; ks < 4; ks++){
            unsigned ah[2][4];
            const int cc2 = ks*2 + csl;
            #pragma unroll
            for(int mt = 0; mt < 2; mt++)
                ldsm4(ah[mt], base + SWZ((wr*32 + mt*16 + rr)*128 + cc2*16));
            #pragma unroll
            for(int hf = 0; hf < 2; hf++){
                unsigned bh[2][4], bl[2][4];
                #pragma unroll
                for(int g = 0; g < 2; g++){
                    unsigned rb = base + 16384 + SWZ((wc*64 + hf*32 + g*16 + rr)*128 + cc2*16);
                    ldsm4(bh[g], rb);
                    ldsm4(bl[g], rb + 16384);
                }
                #pragma unroll
                for(int g = 0; g < 2; g++)
                    #pragma unroll
                    for(int sub = 0; sub < 2; sub++){
                        const int nt = hf*4 + g*2 + sub;
                        #pragma unroll
                        for(int mt = 0; mt < 2; mt++){
                            mma16816(acc[mt][nt], ah[mt], bh[g][sub], bh[g][sub+2]);
                            mma16816(acc[mt][nt], ah[mt], bl[g][sub], bl[g][sub+2]);
                        }
                    }
            }
        }
        __syncthreads();
    }

    // Stage fp16 hi/lo into smem, then coalesced global writes.
    const int part = n0 >> 10;          // 0=K, 1=Q, 2=V
    const int h0   = (n0 & 1023) >> 6;
    const float sc = (part == 1) ? QF_ : 1.0f;
    __half *gh, *gl;
    if(part == 0){ gh = g_Kh;  gl = g_Kl;  }
    else if(part == 1){ gh = g_Qh; gl = g_Kl; }   // lo unused for Q
    else { gh = g_Vth; gl = g_Vtl; }

    #pragma unroll
    for(int mt = 0; mt < 2; mt++)
        #pragma unroll
        for(int nt = 0; nt < 8; nt++){
            const int r0 = wr*32 + mt*16 + (lane >> 2);
            const int cc = wc*64 + nt*8 + (lane & 3)*2;
            float v0 = acc[mt][nt][0]*sc, v1 = acc[mt][nt][1]*sc;
            float v2 = acc[mt][nt][2]*sc, v3 = acc[mt][nt][3]*sc;
            __half h0a = __float2half_rn(v0), h1a = __float2half_rn(v1);
            __half h2a = __float2half_rn(v2), h3a = __float2half_rn(v3);
            *(unsigned*)(sm + r0*272 + cc*2)             = packhh(h0a, h1a);
            *(unsigned*)(sm + (r0+8)*272 + cc*2)         = packhh(h2a, h3a);
            *(unsigned*)(sm + 34816 + r0*272 + cc*2)     = packh(v0-__half2float(h0a), v1-__half2float(h1a));
            *(unsigned*)(sm + 34816 + (r0+8)*272 + cc*2) = packh(v2-__half2float(h2a), v3-__half2float(h3a));
        }
    __syncthreads();

    #pragma unroll
    for(int j = 0; j < 8; j++){
        int i = tid + j*256;
        int r = i >> 4, cc = i & 15;
        int gr = m0 + r;
        int b = gr >> 11, s = gr & 2047;
        int h = h0 + (cc >> 3);
        size_t off = (((size_t)(b*16 + h)*2048 + s)*64) + (size_t)(cc & 7)*8;
        *(uint4*)(gh + off) = *(uint4*)(sm + r*272 + cc*16);
        if(part != 1)
            *(uint4*)(gl + off) = *(uint4*)(sm + 34816 + r*272 + cc*16);
    }
}

// ---------------------------- transpose V -----------------------------------
__global__ __launch_bounds__(256) void transv_kernel(){
    __shared__ __half th[64][72], tl[64][72];
    const int s0 = blockIdx.x * 64, bh = blockIdx.y;
    const size_t ib = (size_t)bh * 131072;
    #pragma unroll
    for(int i = 0; i < 2; i++){
        int e = i*256 + threadIdx.x;
        int r = e >> 3, g = e & 7;
        *(uint4*)&th[r][g*8] = *(const uint4*)(g_Vth + ib + (size_t)(s0 + r)*64 + g*8);
        *(uint4*)&tl[r][g*8] = *(const uint4*)(g_Vtl + ib + (size_t)(s0 + r)*64 + g*8);
    }
    __syncthreads();
    const int d = threadIdx.x >> 2, sg = (threadIdx.x & 3) * 16;
    unsigned uh[4], ul[4];
    #pragma unroll
    for(int half8 = 0; half8 < 2; half8++){
        #pragma unroll
        for(int j = 0; j < 4; j++){
            int jj = half8*4 + j;
            uh[j] = packhh(th[sg+2*jj][d], th[sg+2*jj+1][d]);
            ul[j] = packhh(tl[sg+2*jj][d], tl[sg+2*jj+1][d]);
        }
        __half* oh = g_Vh + ib + (size_t)d * 2048 + s0 + sg + half8*8;
        __half* ol = g_Vl + ib + (size_t)d * 2048 + s0 + sg + half8*8;
        *(uint4*)oh = *(uint4*)uh;
        *(uint4*)ol = *(uint4*)ul;
    }
}

// ------------------------------ attention -----------------------------------
// grid (16, 64): (qtile, bh). 256 thr (8 warps, 16 q-rows each).
// smem: QH @0 (16K). Stage s (32768 B each) @16384: KH +0, KL +8K, VH +16K, VL +24K.
// ASM = 16384 + 65536 = 81920.
#define ASM 81920

__global__ __launch_bounds__(256) void attn_kernel(float* __restrict__ out){
    extern __shared__ char sm[];
    const unsigned sb = su32(sm);
    const int tid = threadIdx.x, lane = tid & 31, w = tid >> 5;
    const int qt = blockIdx.x, bh = blockIdx.y;
    const int h = bh & 15, b = bh >> 4;
    const int i0 = qt * 128;
    const size_t ib = (size_t)bh * 131072;

    const float slope = exp2f(-0.5f * (float)(h + 1));
    const float c2 = slope * 1.4426950408889634f;

    // load Q tile (plain stores, swizzled)
    #pragma unroll
    for(int j = 0; j < 4; j++){
        int i = tid + j*256;
        int r = i >> 3, ch = i & 7;
        unsigned o = SWZ(r*128 + ch*16);
        *(uint4*)(sm + o) = *(const uint4*)(g_Qh + ib + (size_t)(i0 + r)*64 + ch*8);
    }

    int kt0 = 0;
    while(kt0 < 31 && c2 * (float)(1984 - 64*kt0) > 43.0f) kt0++;
    const int nch = 32 - kt0;

    const int lr = tid >> 3, lch = tid & 7;     // lr 0..31
    #define A_ISSUE(kt, st) do{ \
        const int j0_ = (kt) * 64; \
        const unsigned base_ = sb + 16384 + (st) * 32768; \
        _Pragma("unroll") \
        for(int j_ = 0; j_ < 2; j_++){ \
            int r_ = lr + j_*32; \
            unsigned o_ = SWZ(r_*128 + lch*16); \
            size_t gk_ = ib + (size_t)(j0_ + r_)*64 + lch*8; \
            size_t gv_ = ib + (size_t)r_*2048 + j0_ + lch*8; \
            cpa16(base_ + o_,         g_Kh + gk_); \
            cpa16(base_ + 8192 + o_,  g_Kl + gk_); \
            cpa16(base_ + 16384 + o_, g_Vh + gv_); \
            cpa16(base_ + 24576 + o_, g_Vl + gv_); \
        } \
        CP_COMMIT(); \
    }while(0)

    A_ISSUE(kt0, 0);
    __syncthreads();   // Q visible

    const int rr  = (lane & 7) + ((lane >> 3) & 1) * 8;
    const int csl = lane >> 4;

    unsigned qh[4][4];
    #pragma unroll
    for(int ks = 0; ks < 4; ks++)
        ldsm4(qh[ks], sb + SWZ((w*16 + rr)*128 + (ks*2 + csl)*16));

    float o_[8][4];
    #pragma unroll
    for(int a=0;a<8;a++)
        #pragma unroll
        for(int e=0;e<4;e++) o_[a][e]=0.0f;
    float l0 = 0.0f, l1 = 0.0f;

    for(int ci = 0; ci < nch; ci++){
        const int kt = kt0 + ci;
        const int j0 = kt * 64;
        if(ci + 1 < nch){ A_ISSUE(kt + 1, (ci + 1) & 1); CP_WAIT1(); }
        else            { CP_WAIT0(); }
        __syncthreads();
        const unsigned base = sb + 16384 + (ci & 1) * 32768;

        // S = Q @ K^T  (2-split: Qh*Kh + Qh*Kl)
        float s_[8][4];
        #pragma unroll
        for(int a=0;a<8;a++)
            #pragma unroll
            for(int e=0;e<4;e++) s_[a][e]=0.0f;
        #pragma unroll
        for(int ks = 0; ks < 4; ks++){
            unsigned kbh[4][4], kbl[4][4];
            #pragma unroll
            for(int g = 0; g < 4; g++){
                unsigned rb = base + SWZ((g*16 + rr)*128 + (ks*2 + csl)*16);
                ldsm4(kbh[g], rb);
                ldsm4(kbl[g], rb + 8192);
            }
            #pragma unroll
            for(int g = 0; g < 4; g++)
                #pragma unroll
                for(int sub = 0; sub < 2; sub++){
                    const int nt = g*2 + sub;
                    mma16816(s_[nt], qh[ks], kbh[g][sub], kbh[g][sub+2]);
                    mma16816(s_[nt], qh[ks], kbl[g][sub], kbl[g][sub+2]);
                }
        }

        // exp2 with analytic shift; build P fragments (hi/lo fp16)
        unsigned ph[4][4], pl[4][4];
        #pragma unroll
        for(int nt = 0; nt < 8; nt++){
            const float jb = (float)(j0 + nt*8 + (lane & 3)*2 - 2047);
            float p0 = ex2f(fmaf(c2, jb,        s_[nt][0]));
            float p1 = ex2f(fmaf(c2, jb + 1.0f, s_[nt][1]));
            float p2 = ex2f(fmaf(c2, jb,        s_[nt][2]));
            float p3 = ex2f(fmaf(c2, jb + 1.0f, s_[nt][3]));
            l0 += p0 + p1;
            l1 += p2 + p3;
            __half h0a = __float2half_rn(p0), h1a = __float2half_rn(p1);
            __half h2a = __float2half_rn(p2), h3a = __float2half_rn(p3);
            const int kk = nt >> 1, od = nt & 1;
            ph[kk][od ? 2 : 0] = packhh(h0a, h1a);
            ph[kk][od ? 3 : 1] = packhh(h2a, h3a);
            pl[kk][od ? 2 : 0] = packh(p0-__half2float(h0a), p1-__half2float(h1a));
            pl[kk][od ? 3 : 1] = packh(p2-__half2float(h2a), p3-__half2float(h3a));
        }

        // O += P @ V  (V stored [d][s]; 3-split)
        #pragma unroll
        for(int kk = 0; kk < 4; kk++){
            unsigned vbh[4][4], vbl[4][4];
            #pragma unroll
            for(int g = 0; g < 4; g++){
                unsigned rb = base + 16384 + SWZ((g*16 + rr)*128 + (kk*2 + csl)*16);
                ldsm4(vbh[g], rb);
                ldsm4(vbl[g], rb + 8192);
            }
            #pragma unroll
            for(int g = 0; g < 4; g++)
                #pragma unroll
                for(int sub = 0; sub < 2; sub++){
                    const int nt = g*2 + sub;
                    mma16816(o_[nt], ph[kk], vbh[g][sub], vbh[g][sub+2]);
                    mma16816(o_[nt], pl[kk], vbh[g][sub], vbh[g][sub+2]);
                    mma16816(o_[nt], ph[kk], vbl[g][sub], vbl[g][sub+2]);
                }
        }
        __syncthreads();
    }

    // reduce l within quads
    l0 += __shfl_xor_sync(0xffffffffu, l0, 1);
    l0 += __shfl_xor_sync(0xffffffffu, l0, 2);
    l1 += __shfl_xor_sync(0xffffffffu, l1, 1);
    l1 += __shfl_xor_sync(0xffffffffu, l1, 2);
    const float inv0 = 1.0f / l0, inv1 = 1.0f / l1;

    const int r0g = i0 + w*16 + (lane >> 2);
    float* op0 = out + ((size_t)b*2048 + r0g)*1024 + h*64 + (lane & 3)*2;
    float* op1 = out + ((size_t)b*2048 + r0g + 8)*1024 + h*64 + (lane & 3)*2;
    #pragma unroll
    for(int nt = 0; nt < 8; nt++){
        *(float2*)(op0 + nt*8) = make_float2(o_[nt][0]*inv0, o_[nt][1]*inv0);
        *(float2*)(op1 + nt*8) = make_float2(o_[nt][2]*inv1, o_[nt][3]*inv1);
    }
}

// ------------------------------- launch --------------------------------------
extern "C" void kernel_launch(void* const* d_in, const int* in_sizes, int n_in,
                              void* d_out, int out_size)
{
    const float* x = (const float*)d_in[0];
    const float* w = (const float*)d_in[1];
    float* out = (float*)d_out;
    (void)in_sizes; (void)n_in; (void)out_size;

    splitx_kernel<<<4096, 256>>>(x);
    splitw_kernel<<<dim3(48, 16), 256>>>(w);

    cudaFuncSetAttribute(gemm_kernel, cudaFuncAttributeMaxDynamicSharedMemorySize, GSM);
    gemm_kernel<<<dim3(24, 64), 256, GSM>>>();

    transv_kernel<<<dim3(32, 64), 256>>>();

    cudaFuncSetAttribute(attn_kernel, cudaFuncAttributeMaxDynamicSharedMemorySize, ASM);
    attn_kernel<<<dim3(16, 64), 256, ASM>>>(out);
}

// round 8
// speedup vs baseline: 7.7654x; 1.1936x over previous
#include <cuda_runtime.h>
#include <cuda_fp16.h>
#include <math.h>

#define QF_ 0.04508422002777998f   // log2(e)/32

// ------------------------- device scratch (no allocs) ----------------------
__device__ __half g_Xh[(size_t)8192*1024];
__device__ __half g_Wh[(size_t)3072*1024];   // W^T [n][k]
__device__ __half g_Wl[(size_t)3072*1024];
__device__ __half g_Qh[(size_t)64*2048*64];  // [bh][s][d] (pre-scaled by QF)
__device__ __half g_Kh[(size_t)64*2048*64];
__device__ __half g_Kl[(size_t)64*2048*64];
__device__ __half g_Vsh[(size_t)64*2048*64]; // [bh][s][d]
__device__ __half g_Vsl[(size_t)64*2048*64];

// ------------------------------ helpers ------------------------------------
__device__ __forceinline__ unsigned su32(const void* p){
    unsigned a;
    asm("{ .reg .u64 t; cvta.to.shared.u64 t, %1; cvt.u32.u64 %0, t; }":"=r"(a):"l"(p));
    return a;
}
#define SWZ(o) ((unsigned)(o) ^ ((((unsigned)(o)) >> 3) & 0x70))

__device__ __forceinline__ void cpa16(unsigned dst, const void* src){
    asm volatile("cp.async.cg.shared.global [%0], [%1], 16;"::"r"(dst),"l"(src));
}
#define CP_COMMIT() asm volatile("cp.async.commit_group;" ::: "memory")
#define CP_WAIT1()  asm volatile("cp.async.wait_group 1;" ::: "memory")
#define CP_WAIT0()  asm volatile("cp.async.wait_group 0;" ::: "memory")

__device__ __forceinline__ void ldsm4(unsigned* r, unsigned a){
    asm volatile("ldmatrix.sync.aligned.m8n8.x4.shared.b16 {%0,%1,%2,%3}, [%4];"
                 : "=r"(r[0]),"=r"(r[1]),"=r"(r[2]),"=r"(r[3]) : "r"(a));
}
__device__ __forceinline__ void ldsm4t(unsigned* r, unsigned a){
    asm volatile("ldmatrix.sync.aligned.m8n8.x4.trans.shared.b16 {%0,%1,%2,%3}, [%4];"
                 : "=r"(r[0]),"=r"(r[1]),"=r"(r[2]),"=r"(r[3]) : "r"(a));
}
__device__ __forceinline__ void mma16816(float* d, const unsigned* a, unsigned b0, unsigned b1){
    asm volatile("mma.sync.aligned.m16n8k16.row.col.f32.f16.f16.f32 "
                 "{%0,%1,%2,%3},{%4,%5,%6,%7},{%8,%9},{%0,%1,%2,%3};"
                 : "+f"(d[0]),"+f"(d[1]),"+f"(d[2]),"+f"(d[3])
                 : "r"(a[0]),"r"(a[1]),"r"(a[2]),"r"(a[3]),"r"(b0),"r"(b1));
}
__device__ __forceinline__ float ex2f(float x){
    float r; asm("ex2.approx.ftz.f32 %0, %1;":"=f"(r):"f"(x)); return r;
}
__device__ __forceinline__ unsigned packh(float a, float b){
    __half2 h = __floats2half2_rn(a, b);
    return *(unsigned*)&h;
}
__device__ __forceinline__ unsigned packhh(__half a, __half b){
    __half2 h = __halves2half2(a, b);
    return *(unsigned*)&h;
}
__device__ __forceinline__ void split8h(const float* v, uint4* H, uint4* L){
    unsigned hw[4], lw[4];
    #pragma unroll
    for(int k=0;k<4;k++){
        __half h0 = __float2half_rn(v[2*k]);
        __half h1 = __float2half_rn(v[2*k+1]);
        hw[k] = packhh(h0, h1);
        lw[k] = packh(v[2*k] - __half2float(h0), v[2*k+1] - __half2float(h1));
    }
    *H = make_uint4(hw[0],hw[1],hw[2],hw[3]);
    *L = make_uint4(lw[0],lw[1],lw[2],lw[3]);
}

// ---------------------------- split X (hi only) ------------------------------
__global__ __launch_bounds__(256) void splitx_kernel(const float* __restrict__ x){
    size_t i = ((size_t)blockIdx.x * 256 + threadIdx.x) * 8;
    float4 a = *(const float4*)(x + i);
    float4 b = *(const float4*)(x + i + 4);
    uint4 H;
    H.x = packh(a.x, a.y); H.y = packh(a.z, a.w);
    H.z = packh(b.x, b.y); H.w = packh(b.z, b.w);
    *(uint4*)(g_Xh + i) = H;
}

// ------------------------ split + transpose W -------------------------------
__global__ __launch_bounds__(256) void splitw_kernel(const float* __restrict__ w){
    __shared__ float ws[64][65];
    const int n0 = blockIdx.x * 64, k0 = blockIdx.y * 64;
    #pragma unroll
    for(int i=0;i<4;i++){
        int e = i*256 + threadIdx.x;
        int r = e >> 4, c4 = (e & 15) * 4;
        float4 t = *(const float4*)(w + (size_t)(k0 + r) * 3072 + n0 + c4);
        ws[r][c4+0]=t.x; ws[r][c4+1]=t.y; ws[r][c4+2]=t.z; ws[r][c4+3]=t.w;
    }
    __syncthreads();
    int n = threadIdx.x >> 2, sg = (threadIdx.x & 3) * 16;
    float v[16];
    #pragma unroll
    for(int j=0;j<16;j++) v[j] = ws[sg + j][n];
    uint4 H0,L0,H1,L1;
    split8h(v, &H0, &L0); split8h(v+8, &H1, &L1);
    __half* dh = g_Wh + (size_t)(n0 + n) * 1024 + k0 + sg;
    __half* dl = g_Wl + (size_t)(n0 + n) * 1024 + k0 + sg;
    *(uint4*)(dh) = H0; *(uint4*)(dh + 8) = H1;
    *(uint4*)(dl) = L0; *(uint4*)(dl + 8) = L1;
}

// ------------------------------ QKV GEMM ------------------------------------
// grid (24, 64), 256 thr. Double-buffered cp.async pipeline.
// Stage s (49152 B each): AH +0 (16K), BH +16K, BL +32K. GSM=98304.
#define GSM 98304

__global__ __launch_bounds__(256) void gemm_kernel(){
    extern __shared__ char sm[];
    const unsigned sb = su32(sm);
    const int tid = threadIdx.x, lane = tid & 31, wid = tid >> 5;
    const int wr = wid & 3, wc = wid >> 2;
    const int m0 = blockIdx.y * 128, n0 = blockIdx.x * 128;

    float acc[2][8][4];
    #pragma unroll
    for(int a=0;a<2;a++)
        #pragma unroll
        for(int b=0;b<8;b++)
            #pragma unroll
            for(int c=0;c<4;c++) acc[a][b][c]=0.0f;

    const int rr  = (lane & 7) + ((lane >> 3) & 1) * 8;
    const int csl = lane >> 4;

    // load-issue index (constant across stages)
    const int lr = tid >> 3, lch = tid & 7;
    const unsigned lo_sw[4] = { SWZ((lr     )*128 + lch*16), SWZ((lr + 32)*128 + lch*16),
                                SWZ((lr + 64)*128 + lch*16), SWZ((lr + 96)*128 + lch*16) };

    #define G_ISSUE(c, st) do{ \
        const int k0_ = (c) * 64; \
        const unsigned base_ = sb + (st) * 49152; \
        _Pragma("unroll") \
        for(int j_ = 0; j_ < 4; j_++){ \
            int r_ = lr + j_*32; \
            unsigned o_ = lo_sw[j_]; \
            cpa16(base_ + o_,         g_Xh + (size_t)(m0 + r_) * 1024 + k0_ + lch*8); \
            cpa16(base_ + 16384 + o_, g_Wh + (size_t)(n0 + r_) * 1024 + k0_ + lch*8); \
            cpa16(base_ + 32768 + o_, g_Wl + (size_t)(n0 + r_) * 1024 + k0_ + lch*8); \
        } \
        CP_COMMIT(); \
    }while(0)

    G_ISSUE(0, 0);

    for(int c = 0; c < 16; c++){
        if(c < 15){ G_ISSUE(c + 1, (c + 1) & 1); CP_WAIT1(); }
        else      { CP_WAIT0(); }
        __syncthreads();
        const unsigned base = sb + (c & 1) * 49152;

        #pragma unroll
        for(int ks = 0; ks < 4; ks++){
            unsigned ah[2][4];
            const int cc2 = ks*2 + csl;
            #pragma unroll
            for(int mt = 0; mt < 2; mt++)
                ldsm4(ah[mt], base + SWZ((wr*32 + mt*16 + rr)*128 + cc2*16));
            #pragma unroll
            for(int hf = 0; hf < 2; hf++){
                unsigned bh[2][4], bl[2][4];
                #pragma unroll
                for(int g = 0; g < 2; g++){
                    unsigned rb = base + 16384 + SWZ((wc*64 + hf*32 + g*16 + rr)*128 + cc2*16);
                    ldsm4(bh[g], rb);
                    ldsm4(bl[g], rb + 16384);
                }
                #pragma unroll
                for(int g = 0; g < 2; g++)
                    #pragma unroll
                    for(int sub = 0; sub < 2; sub++){
                        const int nt = hf*4 + g*2 + sub;
                        #pragma unroll
                        for(int mt = 0; mt < 2; mt++){
                            mma16816(acc[mt][nt], ah[mt], bh[g][sub], bh[g][sub+2]);
                            mma16816(acc[mt][nt], ah[mt], bl[g][sub], bl[g][sub+2]);
                        }
                    }
            }
        }
        __syncthreads();
    }

    // Stage fp16 hi/lo into smem, then coalesced global writes.
    const int part = n0 >> 10;          // 0=K, 1=Q, 2=V
    const int h0   = (n0 & 1023) >> 6;
    const float sc = (part == 1) ? QF_ : 1.0f;
    __half *gh, *gl;
    if(part == 0){ gh = g_Kh;  gl = g_Kl;  }
    else if(part == 1){ gh = g_Qh; gl = g_Kl; }   // lo unused for Q
    else { gh = g_Vsh; gl = g_Vsl; }

    #pragma unroll
    for(int mt = 0; mt < 2; mt++)
        #pragma unroll
        for(int nt = 0; nt < 8; nt++){
            const int r0 = wr*32 + mt*16 + (lane >> 2);
            const int cc = wc*64 + nt*8 + (lane & 3)*2;
            float v0 = acc[mt][nt][0]*sc, v1 = acc[mt][nt][1]*sc;
            float v2 = acc[mt][nt][2]*sc, v3 = acc[mt][nt][3]*sc;
            __half h0a = __float2half_rn(v0), h1a = __float2half_rn(v1);
            __half h2a = __float2half_rn(v2), h3a = __float2half_rn(v3);
            *(unsigned*)(sm + r0*272 + cc*2)             = packhh(h0a, h1a);
            *(unsigned*)(sm + (r0+8)*272 + cc*2)         = packhh(h2a, h3a);
            *(unsigned*)(sm + 34816 + r0*272 + cc*2)     = packh(v0-__half2float(h0a), v1-__half2float(h1a));
            *(unsigned*)(sm + 34816 + (r0+8)*272 + cc*2) = packh(v2-__half2float(h2a), v3-__half2float(h3a));
        }
    __syncthreads();

    #pragma unroll
    for(int j = 0; j < 8; j++){
        int i = tid + j*256;
        int r = i >> 4, cc = i & 15;
        int gr = m0 + r;
        int b = gr >> 11, s = gr & 2047;
        int h = h0 + (cc >> 3);
        size_t off = (((size_t)(b*16 + h)*2048 + s)*64) + (size_t)(cc & 7)*8;
        *(uint4*)(gh + off) = *(uint4*)(sm + r*272 + cc*16);
        if(part != 1)
            *(uint4*)(gl + off) = *(uint4*)(sm + 34816 + r*272 + cc*16);
    }
}

// ------------------------------ attention -----------------------------------
// grid (16, 64): (qtile, bh). 256 thr (8 warps, 16 q-rows each).
// smem: QH @0 (16K). Stage s (32768 B each) @16384: KH +0, KL +8K, VH +16K, VL +24K.
// V tiles stored [s][d] (same as K); PV B-fragments via ldmatrix.trans.
// ASM = 16384 + 65536 = 81920.
#define ASM 81920

__global__ __launch_bounds__(256) void attn_kernel(float* __restrict__ out){
    extern __shared__ char sm[];
    const unsigned sb = su32(sm);
    const int tid = threadIdx.x, lane = tid & 31, w = tid >> 5;
    const int qt = blockIdx.x, bh = blockIdx.y;
    const int h = bh & 15, b = bh >> 4;
    const int i0 = qt * 128;
    const size_t ib = (size_t)bh * 131072;

    const float slope = exp2f(-0.5f * (float)(h + 1));
    const float c2 = slope * 1.4426950408889634f;

    // load Q tile (plain stores, swizzled)
    #pragma unroll
    for(int j = 0; j < 4; j++){
        int i = tid + j*256;
        int r = i >> 3, ch = i & 7;
        unsigned o = SWZ(r*128 + ch*16);
        *(uint4*)(sm + o) = *(const uint4*)(g_Qh + ib + (size_t)(i0 + r)*64 + ch*8);
    }

    int kt0 = 0;
    while(kt0 < 31 && c2 * (float)(1984 - 64*kt0) > 20.0f) kt0++;
    const int nch = 32 - kt0;

    const int lr = tid >> 3, lch = tid & 7;     // lr 0..31
    #define A_ISSUE(kt, st) do{ \
        const int j0_ = (kt) * 64; \
        const unsigned base_ = sb + 16384 + (st) * 32768; \
        _Pragma("unroll") \
        for(int j_ = 0; j_ < 2; j_++){ \
            int r_ = lr + j_*32; \
            unsigned o_ = SWZ(r_*128 + lch*16); \
            size_t gx_ = ib + (size_t)(j0_ + r_)*64 + lch*8; \
            cpa16(base_ + o_,         g_Kh  + gx_); \
            cpa16(base_ + 8192 + o_,  g_Kl  + gx_); \
            cpa16(base_ + 16384 + o_, g_Vsh + gx_); \
            cpa16(base_ + 24576 + o_, g_Vsl + gx_); \
        } \
        CP_COMMIT(); \
    }while(0)

    A_ISSUE(kt0, 0);
    __syncthreads();   // Q visible

    const int rr  = (lane & 7) + ((lane >> 3) & 1) * 8;
    const int csl = lane >> 4;

    unsigned qh[4][4];
    #pragma unroll
    for(int ks = 0; ks < 4; ks++)
        ldsm4(qh[ks], sb + SWZ((w*16 + rr)*128 + (ks*2 + csl)*16));

    float o_[8][4];
    #pragma unroll
    for(int a=0;a<8;a++)
        #pragma unroll
        for(int e=0;e<4;e++) o_[a][e]=0.0f;
    float l0 = 0.0f, l1 = 0.0f;

    for(int ci = 0; ci < nch; ci++){
        const int kt = kt0 + ci;
        const int j0 = kt * 64;
        if(ci + 1 < nch){ A_ISSUE(kt + 1, (ci + 1) & 1); CP_WAIT1(); }
        else            { CP_WAIT0(); }
        __syncthreads();
        const unsigned base = sb + 16384 + (ci & 1) * 32768;

        // S = Q @ K^T  (2-split: Qh*Kh + Qh*Kl)
        float s_[8][4];
        #pragma unroll
        for(int a=0;a<8;a++)
            #pragma unroll
            for(int e=0;e<4;e++) s_[a][e]=0.0f;
        #pragma unroll
        for(int ks = 0; ks < 4; ks++){
            unsigned kbh[4][4], kbl[4][4];
            #pragma unroll
            for(int g = 0; g < 4; g++){
                unsigned rb = base + SWZ((g*16 + rr)*128 + (ks*2 + csl)*16);
                ldsm4(kbh[g], rb);
                ldsm4(kbl[g], rb + 8192);
            }
            #pragma unroll
            for(int g = 0; g < 4; g++)
                #pragma unroll
                for(int sub = 0; sub < 2; sub++){
                    const int nt = g*2 + sub;
                    mma16816(s_[nt], qh[ks], kbh[g][sub], kbh[g][sub+2]);
                    mma16816(s_[nt], qh[ks], kbl[g][sub], kbl[g][sub+2]);
                }
        }

        // exp2 with analytic shift; build P fragments (hi/lo fp16)
        unsigned ph[4][4], pl[4][4];
        #pragma unroll
        for(int nt = 0; nt < 8; nt++){
            const float jb = (float)(j0 + nt*8 + (lane & 3)*2 - 2047);
            float p0 = ex2f(fmaf(c2, jb,        s_[nt][0]));
            float p1 = ex2f(fmaf(c2, jb + 1.0f, s_[nt][1]));
            float p2 = ex2f(fmaf(c2, jb,        s_[nt][2]));
            float p3 = ex2f(fmaf(c2, jb + 1.0f, s_[nt][3]));
            l0 += p0 + p1;
            l1 += p2 + p3;
            __half h0a = __float2half_rn(p0), h1a = __float2half_rn(p1);
            __half h2a = __float2half_rn(p2), h3a = __float2half_rn(p3);
            const int kk = nt >> 1, od = nt & 1;
            ph[kk][od ? 2 : 0] = packhh(h0a, h1a);
            ph[kk][od ? 3 : 1] = packhh(h2a, h3a);
            pl[kk][od ? 2 : 0] = packh(p0-__half2float(h0a), p1-__half2float(h1a));
            pl[kk][od ? 3 : 1] = packh(p2-__half2float(h2a), p3-__half2float(h3a));
        }

        // O += P @ V  (V stored [s][d]; B-fragments via ldmatrix.trans; 3-split)
        #pragma unroll
        for(int kk = 0; kk < 4; kk++){
            unsigned vbh[4][4], vbl[4][4];
            #pragma unroll
            for(int g = 0; g < 4; g++){
                unsigned rb = base + 16384 + SWZ((kk*16 + rr)*128 + (g*2 + csl)*16);
                ldsm4t(vbh[g], rb);
                ldsm4t(vbl[g], rb + 8192);
            }
            #pragma unroll
            for(int g = 0; g < 4; g++)
                #pragma unroll
                for(int sub = 0; sub < 2; sub++){
                    const int nt = g*2 + sub;
                    mma16816(o_[nt], ph[kk], vbh[g][2*sub], vbh[g][2*sub+1]);
                    mma16816(o_[nt], pl[kk], vbh[g][2*sub], vbh[g][2*sub+1]);
                    mma16816(o_[nt], ph[kk], vbl[g][2*sub], vbl[g][2*sub+1]);
                }
        }
        __syncthreads();
    }

    // reduce l within quads
    l0 += __shfl_xor_sync(0xffffffffu, l0, 1);
    l0 += __shfl_xor_sync(0xffffffffu, l0, 2);
    l1 += __shfl_xor_sync(0xffffffffu, l1, 1);
    l1 += __shfl_xor_sync(0xffffffffu, l1, 2);
    const float inv0 = 1.0f / l0, inv1 = 1.0f / l1;

    const int r0g = i0 + w*16 + (lane >> 2);
    float* op0 = out + ((size_t)b*2048 + r0g)*1024 + h*64 + (lane & 3)*2;
    float* op1 = out + ((size_t)b*2048 + r0g + 8)*1024 + h*64 + (lane & 3)*2;
    #pragma unroll
    for(int nt = 0; nt < 8; nt++){
        *(float2*)(op0 + nt*8) = make_float2(o_[nt][0]*inv0, o_[nt][1]*inv0);
        *(float2*)(op1 + nt*8) = make_float2(o_[nt][2]*inv1, o_[nt][3]*inv1);
    }
}

// ------------------------------- launch --------------------------------------
extern "C" void kernel_launch(void* const* d_in, const int* in_sizes, int n_in,
                              void* d_out, int out_size)
{
    const float* x = (const float*)d_in[0];
    const float* w = (const float*)d_in[1];
    float* out = (float*)d_out;
    (void)in_sizes; (void)n_in; (void)out_size;

    splitx_kernel<<<4096, 256>>>(x);
    splitw_kernel<<<dim3(48, 16), 256>>>(w);

    cudaFuncSetAttribute(gemm_kernel, cudaFuncAttributeMaxDynamicSharedMemorySize, GSM);
    gemm_kernel<<<dim3(24, 64), 256, GSM>>>();

    cudaFuncSetAttribute(attn_kernel, cudaFuncAttributeMaxDynamicSharedMemorySize, ASM);
    attn_kernel<<<dim3(16, 64), 256, ASM>>>(out);
}

// round 9
// speedup vs baseline: 11.5790x; 1.4911x over previous
#include <cuda_runtime.h>
#include <cuda_fp16.h>
#include <math.h>

#define QF_ 0.04508422002777998f   // log2(e)/32

// ------------------------- device scratch (no allocs) ----------------------
__device__ __half g_Xh[(size_t)8192*1024];
__device__ __half g_Wh[(size_t)3072*1024];   // W^T [n][k]
__device__ __half g_Qh[(size_t)64*2048*64];  // [bh][s][d] (pre-scaled by QF)
__device__ __half g_Kh[(size_t)64*2048*64];
__device__ __half g_Kl[(size_t)64*2048*64];
__device__ __half g_Vsh[(size_t)64*2048*64]; // [bh][s][d]
__device__ __half g_Vsl[(size_t)64*2048*64];

// ------------------------------ helpers ------------------------------------
__device__ __forceinline__ unsigned su32(const void* p){
    unsigned a;
    asm("{ .reg .u64 t; cvta.to.shared.u64 t, %1; cvt.u32.u64 %0, t; }":"=r"(a):"l"(p));
    return a;
}
#define SWZ(o) ((unsigned)(o) ^ ((((unsigned)(o)) >> 3) & 0x70))

__device__ __forceinline__ void cpa16(unsigned dst, const void* src){
    asm volatile("cp.async.cg.shared.global [%0], [%1], 16;"::"r"(dst),"l"(src));
}
#define CP_COMMIT() asm volatile("cp.async.commit_group;" ::: "memory")
#define CP_WAIT1()  asm volatile("cp.async.wait_group 1;" ::: "memory")
#define CP_WAIT0()  asm volatile("cp.async.wait_group 0;" ::: "memory")

__device__ __forceinline__ void ldsm4(unsigned* r, unsigned a){
    asm volatile("ldmatrix.sync.aligned.m8n8.x4.shared.b16 {%0,%1,%2,%3}, [%4];"
                 : "=r"(r[0]),"=r"(r[1]),"=r"(r[2]),"=r"(r[3]) : "r"(a));
}
__device__ __forceinline__ void ldsm4t(unsigned* r, unsigned a){
    asm volatile("ldmatrix.sync.aligned.m8n8.x4.trans.shared.b16 {%0,%1,%2,%3}, [%4];"
                 : "=r"(r[0]),"=r"(r[1]),"=r"(r[2]),"=r"(r[3]) : "r"(a));
}
__device__ __forceinline__ void mma16816(float* d, const unsigned* a, unsigned b0, unsigned b1){
    asm volatile("mma.sync.aligned.m16n8k16.row.col.f32.f16.f16.f32 "
                 "{%0,%1,%2,%3},{%4,%5,%6,%7},{%8,%9},{%0,%1,%2,%3};"
                 : "+f"(d[0]),"+f"(d[1]),"+f"(d[2]),"+f"(d[3])
                 : "r"(a[0]),"r"(a[1]),"r"(a[2]),"r"(a[3]),"r"(b0),"r"(b1));
}
__device__ __forceinline__ float ex2f(float x){
    float r; asm("ex2.approx.ftz.f32 %0, %1;":"=f"(r):"f"(x)); return r;
}
__device__ __forceinline__ unsigned packh(float a, float b){
    __half2 h = __floats2half2_rn(a, b);
    return *(unsigned*)&h;
}
__device__ __forceinline__ unsigned packhh(__half a, __half b){
    __half2 h = __halves2half2(a, b);
    return *(unsigned*)&h;
}

// ---------------------------- split X (hi only) ------------------------------
__global__ __launch_bounds__(256) void splitx_kernel(const float* __restrict__ x){
    size_t i = ((size_t)blockIdx.x * 256 + threadIdx.x) * 8;
    float4 a = *(const float4*)(x + i);
    float4 b = *(const float4*)(x + i + 4);
    uint4 H;
    H.x = packh(a.x, a.y); H.y = packh(a.z, a.w);
    H.z = packh(b.x, b.y); H.w = packh(b.z, b.w);
    *(uint4*)(g_Xh + i) = H;
}

// -------------------- transpose W (hi only, fp16) ----------------------------
__global__ __launch_bounds__(256) void splitw_kernel(const float* __restrict__ w){
    __shared__ float ws[64][65];
    const int n0 = blockIdx.x * 64, k0 = blockIdx.y * 64;
    #pragma unroll
    for(int i=0;i<4;i++){
        int e = i*256 + threadIdx.x;
        int r = e >> 4, c4 = (e & 15) * 4;
        float4 t = *(const float4*)(w + (size_t)(k0 + r) * 3072 + n0 + c4);
        ws[r][c4+0]=t.x; ws[r][c4+1]=t.y; ws[r][c4+2]=t.z; ws[r][c4+3]=t.w;
    }
    __syncthreads();
    int n = threadIdx.x >> 2, sg = (threadIdx.x & 3) * 16;
    unsigned H[8];
    #pragma unroll
    for(int j=0;j<8;j++)
        H[j] = packh(ws[sg + 2*j][n], ws[sg + 2*j + 1][n]);
    __half* dh = g_Wh + (size_t)(n0 + n) * 1024 + k0 + sg;
    *(uint4*)(dh)     = *(uint4*)(H);
    *(uint4*)(dh + 8) = *(uint4*)(H + 4);
}

// ------------------------------ QKV GEMM ------------------------------------
// grid (24, 64), 256 thr. Double-buffered cp.async pipeline.
// Stage s (32768 B each): AH +0 (16K), BH +16K. Epilogue staging needs 69632.
#define GSM 69632

__global__ __launch_bounds__(256) void gemm_kernel(){
    extern __shared__ char sm[];
    const unsigned sb = su32(sm);
    const int tid = threadIdx.x, lane = tid & 31, wid = tid >> 5;
    const int wr = wid & 3, wc = wid >> 2;
    const int m0 = blockIdx.y * 128, n0 = blockIdx.x * 128;

    float acc[2][8][4];
    #pragma unroll
    for(int a=0;a<2;a++)
        #pragma unroll
        for(int b=0;b<8;b++)
            #pragma unroll
            for(int c=0;c<4;c++) acc[a][b][c]=0.0f;

    const int rr  = (lane & 7) + ((lane >> 3) & 1) * 8;
    const int csl = lane >> 4;

    // load-issue index (constant across stages)
    const int lr = tid >> 3, lch = tid & 7;
    const unsigned lo_sw[4] = { SWZ((lr     )*128 + lch*16), SWZ((lr + 32)*128 + lch*16),
                                SWZ((lr + 64)*128 + lch*16), SWZ((lr + 96)*128 + lch*16) };

    #define G_ISSUE(c, st) do{ \
        const int k0_ = (c) * 64; \
        const unsigned base_ = sb + (st) * 32768; \
        _Pragma("unroll") \
        for(int j_ = 0; j_ < 4; j_++){ \
            int r_ = lr + j_*32; \
            unsigned o_ = lo_sw[j_]; \
            cpa16(base_ + o_,         g_Xh + (size_t)(m0 + r_) * 1024 + k0_ + lch*8); \
            cpa16(base_ + 16384 + o_, g_Wh + (size_t)(n0 + r_) * 1024 + k0_ + lch*8); \
        } \
        CP_COMMIT(); \
    }while(0)

    G_ISSUE(0, 0);

    for(int c = 0; c < 16; c++){
        if(c < 15){ G_ISSUE(c + 1, (c + 1) & 1); CP_WAIT1(); }
        else      { CP_WAIT0(); }
        __syncthreads();
        const unsigned base = sb + (c & 1) * 32768;

        #pragma unroll
        for(int ks = 0; ks < 4; ks++){
            unsigned ah[2][4];
            const int cc2 = ks*2 + csl;
            #pragma unroll
            for(int mt = 0; mt < 2; mt++)
                ldsm4(ah[mt], base + SWZ((wr*32 + mt*16 + rr)*128 + cc2*16));
            #pragma unroll
            for(int hf = 0; hf < 2; hf++){
                unsigned bh[2][4];
                #pragma unroll
                for(int g = 0; g < 2; g++)
                    ldsm4(bh[g], base + 16384 + SWZ((wc*64 + hf*32 + g*16 + rr)*128 + cc2*16));
                #pragma unroll
                for(int g = 0; g < 2; g++)
                    #pragma unroll
                    for(int sub = 0; sub < 2; sub++){
                        const int nt = hf*4 + g*2 + sub;
                        #pragma unroll
                        for(int mt = 0; mt < 2; mt++)
                            mma16816(acc[mt][nt], ah[mt], bh[g][sub], bh[g][sub+2]);
                    }
            }
        }
        __syncthreads();
    }

    // Stage fp16 hi/lo into smem, then coalesced global writes.
    const int part = n0 >> 10;          // 0=K, 1=Q, 2=V
    const int h0   = (n0 & 1023) >> 6;
    const float sc = (part == 1) ? QF_ : 1.0f;
    __half *gh, *gl;
    if(part == 0){ gh = g_Kh;  gl = g_Kl;  }
    else if(part == 1){ gh = g_Qh; gl = g_Kl; }   // lo unused for Q
    else { gh = g_Vsh; gl = g_Vsl; }

    #pragma unroll
    for(int mt = 0; mt < 2; mt++)
        #pragma unroll
        for(int nt = 0; nt < 8; nt++){
            const int r0 = wr*32 + mt*16 + (lane >> 2);
            const int cc = wc*64 + nt*8 + (lane & 3)*2;
            float v0 = acc[mt][nt][0]*sc, v1 = acc[mt][nt][1]*sc;
            float v2 = acc[mt][nt][2]*sc, v3 = acc[mt][nt][3]*sc;
            __half h0a = __float2half_rn(v0), h1a = __float2half_rn(v1);
            __half h2a = __float2half_rn(v2), h3a = __float2half_rn(v3);
            *(unsigned*)(sm + r0*272 + cc*2)             = packhh(h0a, h1a);
            *(unsigned*)(sm + (r0+8)*272 + cc*2)         = packhh(h2a, h3a);
            *(unsigned*)(sm + 34816 + r0*272 + cc*2)     = packh(v0-__half2float(h0a), v1-__half2float(h1a));
            *(unsigned*)(sm + 34816 + (r0+8)*272 + cc*2) = packh(v2-__half2float(h2a), v3-__half2float(h3a));
        }
    __syncthreads();

    #pragma unroll
    for(int j = 0; j < 8; j++){
        int i = tid + j*256;
        int r = i >> 4, cc = i & 15;
        int gr = m0 + r;
        int b = gr >> 11, s = gr & 2047;
        int h = h0 + (cc >> 3);
        size_t off = (((size_t)(b*16 + h)*2048 + s)*64) + (size_t)(cc & 7)*8;
        *(uint4*)(gh + off) = *(uint4*)(sm + r*272 + cc*16);
        if(part != 1)
            *(uint4*)(gl + off) = *(uint4*)(sm + 34816 + r*272 + cc*16);
    }
}

// ------------------------------ attention -----------------------------------
// grid (16, 64): (qtile, bh). 256 thr (8 warps, 16 q-rows each).
// smem: QH @0 (16K). Stage s (32768 B each) @16384: KH +0, KL +8K, VH +16K, VL +24K.
// V tiles stored [s][d] (same as K); PV B-fragments via ldmatrix.trans.
// ASM = 16384 + 65536 = 81920.
#define ASM 81920

__global__ __launch_bounds__(256) void attn_kernel(float* __restrict__ out){
    extern __shared__ char sm[];
    const unsigned sb = su32(sm);
    const int tid = threadIdx.x, lane = tid & 31, w = tid >> 5;
    const int qt = blockIdx.x, bh = blockIdx.y;
    const int h = bh & 15, b = bh >> 4;
    const int i0 = qt * 128;
    const size_t ib = (size_t)bh * 131072;

    const float slope = exp2f(-0.5f * (float)(h + 1));
    const float c2 = slope * 1.4426950408889634f;

    // load Q tile (plain stores, swizzled)
    #pragma unroll
    for(int j = 0; j < 4; j++){
        int i = tid + j*256;
        int r = i >> 3, ch = i & 7;
        unsigned o = SWZ(r*128 + ch*16);
        *(uint4*)(sm + o) = *(const uint4*)(g_Qh + ib + (size_t)(i0 + r)*64 + ch*8);
    }

    int kt0 = 0;
    while(kt0 < 31 && c2 * (float)(1984 - 64*kt0) > 20.0f) kt0++;
    const int nch = 32 - kt0;

    const int lr = tid >> 3, lch = tid & 7;     // lr 0..31
    #define A_ISSUE(kt, st) do{ \
        const int j0_ = (kt) * 64; \
        const unsigned base_ = sb + 16384 + (st) * 32768; \
        _Pragma("unroll") \
        for(int j_ = 0; j_ < 2; j_++){ \
            int r_ = lr + j_*32; \
            unsigned o_ = SWZ(r_*128 + lch*16); \
            size_t gx_ = ib + (size_t)(j0_ + r_)*64 + lch*8; \
            cpa16(base_ + o_,         g_Kh  + gx_); \
            cpa16(base_ + 8192 + o_,  g_Kl  + gx_); \
            cpa16(base_ + 16384 + o_, g_Vsh + gx_); \
            cpa16(base_ + 24576 + o_, g_Vsl + gx_); \
        } \
        CP_COMMIT(); \
    }while(0)

    A_ISSUE(kt0, 0);
    __syncthreads();   // Q visible

    const int rr  = (lane & 7) + ((lane >> 3) & 1) * 8;
    const int csl = lane >> 4;

    unsigned qh[4][4];
    #pragma unroll
    for(int ks = 0; ks < 4; ks++)
        ldsm4(qh[ks], sb + SWZ((w*16 + rr)*128 + (ks*2 + csl)*16));

    float o_[8][4];
    #pragma unroll
    for(int a=0;a<8;a++)
        #pragma unroll
        for(int e=0;e<4;e++) o_[a][e]=0.0f;
    float l0 = 0.0f, l1 = 0.0f;

    for(int ci = 0; ci < nch; ci++){
        const int kt = kt0 + ci;
        const int j0 = kt * 64;
        if(ci + 1 < nch){ A_ISSUE(kt + 1, (ci + 1) & 1); CP_WAIT1(); }
        else            { CP_WAIT0(); }
        __syncthreads();
        const unsigned base = sb + 16384 + (ci & 1) * 32768;

        // S = Q @ K^T  (2-split: Qh*Kh + Qh*Kl)
        float s_[8][4];
        #pragma unroll
        for(int a=0;a<8;a++)
            #pragma unroll
            for(int e=0;e<4;e++) s_[a][e]=0.0f;
        #pragma unroll
        for(int ks = 0; ks < 4; ks++){
            unsigned kbh[4][4], kbl[4][4];
            #pragma unroll
            for(int g = 0; g < 4; g++){
                unsigned rb = base + SWZ((g*16 + rr)*128 + (ks*2 + csl)*16);
                ldsm4(kbh[g], rb);
                ldsm4(kbl[g], rb + 8192);
            }
            #pragma unroll
            for(int g = 0; g < 4; g++)
                #pragma unroll
                for(int sub = 0; sub < 2; sub++){
                    const int nt = g*2 + sub;
                    mma16816(s_[nt], qh[ks], kbh[g][sub], kbh[g][sub+2]);
                    mma16816(s_[nt], qh[ks], kbl[g][sub], kbl[g][sub+2]);
                }
        }

        // exp2 with analytic shift; build P fragments (hi fp16 only)
        unsigned ph[4][4];
        #pragma unroll
        for(int nt = 0; nt < 8; nt++){
            const float jb = (float)(j0 + nt*8 + (lane & 3)*2 - 2047);
            float p0 = ex2f(fmaf(c2, jb,        s_[nt][0]));
            float p1 = ex2f(fmaf(c2, jb + 1.0f, s_[nt][1]));
            float p2 = ex2f(fmaf(c2, jb,        s_[nt][2]));
            float p3 = ex2f(fmaf(c2, jb + 1.0f, s_[nt][3]));
            l0 += p0 + p1;
            l1 += p2 + p3;
            const int kk = nt >> 1, od = nt & 1;
            ph[kk][od ? 2 : 0] = packh(p0, p1);
            ph[kk][od ? 3 : 1] = packh(p2, p3);
        }

        // O += P @ V  (V stored [s][d]; B-fragments via ldmatrix.trans; 2-split on V)
        #pragma unroll
        for(int kk = 0; kk < 4; kk++){
            unsigned vbh[4][4], vbl[4][4];
            #pragma unroll
            for(int g = 0; g < 4; g++){
                unsigned rb = base + 16384 + SWZ((kk*16 + rr)*128 + (g*2 + csl)*16);
                ldsm4t(vbh[g], rb);
                ldsm4t(vbl[g], rb + 8192);
            }
            #pragma unroll
            for(int g = 0; g < 4; g++)
                #pragma unroll
                for(int sub = 0; sub < 2; sub++){
                    const int nt = g*2 + sub;
                    mma16816(o_[nt], ph[kk], vbh[g][2*sub], vbh[g][2*sub+1]);
                    mma16816(o_[nt], ph[kk], vbl[g][2*sub], vbl[g][2*sub+1]);
                }
        }
        __syncthreads();
    }

    // reduce l within quads
    l0 += __shfl_xor_sync(0xffffffffu, l0, 1);
    l0 += __shfl_xor_sync(0xffffffffu, l0, 2);
    l1 += __shfl_xor_sync(0xffffffffu, l1, 1);
    l1 += __shfl_xor_sync(0xffffffffu, l1, 2);
    const float inv0 = 1.0f / l0, inv1 = 1.0f / l1;

    const int r0g = i0 + w*16 + (lane >> 2);
    float* op0 = out + ((size_t)b*2048 + r0g)*1024 + h*64 + (lane & 3)*2;
    float* op1 = out + ((size_t)b*2048 + r0g + 8)*1024 + h*64 + (lane & 3)*2;
    #pragma unroll
    for(int nt = 0; nt < 8; nt++){
        *(float2*)(op0 + nt*8) = make_float2(o_[nt][0]*inv0, o_[nt][1]*inv0);
        *(float2*)(op1 + nt*8) = make_float2(o_[nt][2]*inv1, o_[nt][3]*inv1);
    }
}

// ------------------------------- launch --------------------------------------
extern "C" void kernel_launch(void* const* d_in, const int* in_sizes, int n_in,
                              void* d_out, int out_size)
{
    const float* x = (const float*)d_in[0];
    const float* w = (const float*)d_in[1];
    float* out = (float*)d_out;
    (void)in_sizes; (void)n_in; (void)out_size;

    splitx_kernel<<<4096, 256>>>(x);
    splitw_kernel<<<dim3(48, 16), 256>>>(w);

    cudaFuncSetAttribute(gemm_kernel, cudaFuncAttributeMaxDynamicSharedMemorySize, GSM);
    gemm_kernel<<<dim3(24, 64), 256, GSM>>>();

    cudaFuncSetAttribute(attn_kernel, cudaFuncAttributeMaxDynamicSharedMemorySize, ASM);
    attn_kernel<<<dim3(16, 64), 256, ASM>>>(out);
}

// round 10
// speedup vs baseline: 14.3728x; 1.2413x over previous
#include <cuda_runtime.h>
#include <cuda_fp16.h>
#include <math.h>

#define QF_ 0.04508422002777998f   // log2(e)/32

// ------------------------- device scratch (no allocs) ----------------------
__device__ __half g_Xh[(size_t)8192*1024];
__device__ __half g_Wh[(size_t)3072*1024];   // W^T [n][k]
__device__ __half g_Qh[(size_t)64*2048*64];  // [bh][s][d] (pre-scaled by QF)
__device__ __half g_Kh[(size_t)64*2048*64];
__device__ __half g_Vsh[(size_t)64*2048*64]; // [bh][s][d]

// ------------------------------ helpers ------------------------------------
__device__ __forceinline__ unsigned su32(const void* p){
    unsigned a;
    asm("{ .reg .u64 t; cvta.to.shared.u64 t, %1; cvt.u32.u64 %0, t; }":"=r"(a):"l"(p));
    return a;
}
#define SWZ(o) ((unsigned)(o) ^ ((((unsigned)(o)) >> 3) & 0x70))

__device__ __forceinline__ void cpa16(unsigned dst, const void* src){
    asm volatile("cp.async.cg.shared.global [%0], [%1], 16;"::"r"(dst),"l"(src));
}
#define CP_COMMIT() asm volatile("cp.async.commit_group;" ::: "memory")
#define CP_WAIT1()  asm volatile("cp.async.wait_group 1;" ::: "memory")
#define CP_WAIT0()  asm volatile("cp.async.wait_group 0;" ::: "memory")

__device__ __forceinline__ void ldsm4(unsigned* r, unsigned a){
    asm volatile("ldmatrix.sync.aligned.m8n8.x4.shared.b16 {%0,%1,%2,%3}, [%4];"
                 : "=r"(r[0]),"=r"(r[1]),"=r"(r[2]),"=r"(r[3]) : "r"(a));
}
__device__ __forceinline__ void ldsm4t(unsigned* r, unsigned a){
    asm volatile("ldmatrix.sync.aligned.m8n8.x4.trans.shared.b16 {%0,%1,%2,%3}, [%4];"
                 : "=r"(r[0]),"=r"(r[1]),"=r"(r[2]),"=r"(r[3]) : "r"(a));
}
__device__ __forceinline__ void mma16816(float* d, const unsigned* a, unsigned b0, unsigned b1){
    asm volatile("mma.sync.aligned.m16n8k16.row.col.f32.f16.f16.f32 "
                 "{%0,%1,%2,%3},{%4,%5,%6,%7},{%8,%9},{%0,%1,%2,%3};"
                 : "+f"(d[0]),"+f"(d[1]),"+f"(d[2]),"+f"(d[3])
                 : "r"(a[0]),"r"(a[1]),"r"(a[2]),"r"(a[3]),"r"(b0),"r"(b1));
}
__device__ __forceinline__ float ex2f(float x){
    float r; asm("ex2.approx.ftz.f32 %0, %1;":"=f"(r):"f"(x)); return r;
}
__device__ __forceinline__ unsigned packh(float a, float b){
    __half2 h = __floats2half2_rn(a, b);
    return *(unsigned*)&h;
}

// ---------------------------- split X (hi only) ------------------------------
__global__ __launch_bounds__(256) void splitx_kernel(const float* __restrict__ x){
    size_t i = ((size_t)blockIdx.x * 256 + threadIdx.x) * 8;
    float4 a = *(const float4*)(x + i);
    float4 b = *(const float4*)(x + i + 4);
    uint4 H;
    H.x = packh(a.x, a.y); H.y = packh(a.z, a.w);
    H.z = packh(b.x, b.y); H.w = packh(b.z, b.w);
    *(uint4*)(g_Xh + i) = H;
}

// -------------------- transpose W (hi only, fp16) ----------------------------
__global__ __launch_bounds__(256) void splitw_kernel(const float* __restrict__ w){
    __shared__ float ws[64][65];
    const int n0 = blockIdx.x * 64, k0 = blockIdx.y * 64;
    #pragma unroll
    for(int i=0;i<4;i++){
        int e = i*256 + threadIdx.x;
        int r = e >> 4, c4 = (e & 15) * 4;
        float4 t = *(const float4*)(w + (size_t)(k0 + r) * 3072 + n0 + c4);
        ws[r][c4+0]=t.x; ws[r][c4+1]=t.y; ws[r][c4+2]=t.z; ws[r][c4+3]=t.w;
    }
    __syncthreads();
    int n = threadIdx.x >> 2, sg = (threadIdx.x & 3) * 16;
    unsigned H[8];
    #pragma unroll
    for(int j=0;j<8;j++)
        H[j] = packh(ws[sg + 2*j][n], ws[sg + 2*j + 1][n]);
    __half* dh = g_Wh + (size_t)(n0 + n) * 1024 + k0 + sg;
    *(uint4*)(dh)     = *(uint4*)(H);
    *(uint4*)(dh + 8) = *(uint4*)(H + 4);
}

// ------------------------------ QKV GEMM ------------------------------------
// grid (24, 64), 256 thr. Double-buffered cp.async pipeline.
// Stage s (32768 B each): AH +0 (16K), BH +16K. Epilogue staging 34816 B.
#define GSM 65536

__global__ __launch_bounds__(256) void gemm_kernel(){
    extern __shared__ char sm[];
    const unsigned sb = su32(sm);
    const int tid = threadIdx.x, lane = tid & 31, wid = tid >> 5;
    const int wr = wid & 3, wc = wid >> 2;
    const int m0 = blockIdx.y * 128, n0 = blockIdx.x * 128;

    float acc[2][8][4];
    #pragma unroll
    for(int a=0;a<2;a++)
        #pragma unroll
        for(int b=0;b<8;b++)
            #pragma unroll
            for(int c=0;c<4;c++) acc[a][b][c]=0.0f;

    const int rr  = (lane & 7) + ((lane >> 3) & 1) * 8;
    const int csl = lane >> 4;

    // load-issue index (constant across stages)
    const int lr = tid >> 3, lch = tid & 7;
    const unsigned lo_sw[4] = { SWZ((lr     )*128 + lch*16), SWZ((lr + 32)*128 + lch*16),
                                SWZ((lr + 64)*128 + lch*16), SWZ((lr + 96)*128 + lch*16) };

    #define G_ISSUE(c, st) do{ \
        const int k0_ = (c) * 64; \
        const unsigned base_ = sb + (st) * 32768; \
        _Pragma("unroll") \
        for(int j_ = 0; j_ < 4; j_++){ \
            int r_ = lr + j_*32; \
            unsigned o_ = lo_sw[j_]; \
            cpa16(base_ + o_,         g_Xh + (size_t)(m0 + r_) * 1024 + k0_ + lch*8); \
            cpa16(base_ + 16384 + o_, g_Wh + (size_t)(n0 + r_) * 1024 + k0_ + lch*8); \
        } \
        CP_COMMIT(); \
    }while(0)

    G_ISSUE(0, 0);

    for(int c = 0; c < 16; c++){
        if(c < 15){ G_ISSUE(c + 1, (c + 1) & 1); CP_WAIT1(); }
        else      { CP_WAIT0(); }
        __syncthreads();
        const unsigned base = sb + (c & 1) * 32768;

        #pragma unroll
        for(int ks = 0; ks < 4; ks++){
            unsigned ah[2][4];
            const int cc2 = ks*2 + csl;
            #pragma unroll
            for(int mt = 0; mt < 2; mt++)
                ldsm4(ah[mt], base + SWZ((wr*32 + mt*16 + rr)*128 + cc2*16));
            #pragma unroll
            for(int hf = 0; hf < 2; hf++){
                unsigned bh[2][4];
                #pragma unroll
                for(int g = 0; g < 2; g++)
                    ldsm4(bh[g], base + 16384 + SWZ((wc*64 + hf*32 + g*16 + rr)*128 + cc2*16));
                #pragma unroll
                for(int g = 0; g < 2; g++)
                    #pragma unroll
                    for(int sub = 0; sub < 2; sub++){
                        const int nt = hf*4 + g*2 + sub;
                        #pragma unroll
                        for(int mt = 0; mt < 2; mt++)
                            mma16816(acc[mt][nt], ah[mt], bh[g][sub], bh[g][sub+2]);
                    }
            }
        }
        __syncthreads();
    }

    // Stage fp16 (hi only) into smem, then coalesced global writes.
    const int part = n0 >> 10;          // 0=K, 1=Q, 2=V
    const int h0   = (n0 & 1023) >> 6;
    const float sc = (part == 1) ? QF_ : 1.0f;
    __half* gh = (part == 0) ? g_Kh : (part == 1) ? g_Qh : g_Vsh;

    #pragma unroll
    for(int mt = 0; mt < 2; mt++)
        #pragma unroll
        for(int nt = 0; nt < 8; nt++){
            const int r0 = wr*32 + mt*16 + (lane >> 2);
            const int cc = wc*64 + nt*8 + (lane & 3)*2;
            *(unsigned*)(sm + r0*272 + cc*2)     = packh(acc[mt][nt][0]*sc, acc[mt][nt][1]*sc);
            *(unsigned*)(sm + (r0+8)*272 + cc*2) = packh(acc[mt][nt][2]*sc, acc[mt][nt][3]*sc);
        }
    __syncthreads();

    #pragma unroll
    for(int j = 0; j < 8; j++){
        int i = tid + j*256;
        int r = i >> 4, cc = i & 15;
        int gr = m0 + r;
        int b = gr >> 11, s = gr & 2047;
        int h = h0 + (cc >> 3);
        size_t off = (((size_t)(b*16 + h)*2048 + s)*64) + (size_t)(cc & 7)*8;
        *(uint4*)(gh + off) = *(uint4*)(sm + r*272 + cc*16);
    }
}

// ------------------------------ attention -----------------------------------
// grid (16, 64): (qtile, bh). 256 thr (8 warps, 16 q-rows each). Pure fp16.
// smem: QH @0 (16K). Stage s (16384 B each) @16384: KH +0, VH +8K.
// ASM = 16384 + 32768 = 49152.
#define ASM 49152

__global__ __launch_bounds__(256,2) void attn_kernel(float* __restrict__ out){
    extern __shared__ char sm[];
    const unsigned sb = su32(sm);
    const int tid = threadIdx.x, lane = tid & 31, w = tid >> 5;
    const int qt = blockIdx.x, bh = blockIdx.y;
    const int h = bh & 15, b = bh >> 4;
    const int i0 = qt * 128;
    const size_t ib = (size_t)bh * 131072;

    const float slope = exp2f(-0.5f * (float)(h + 1));
    const float c2 = slope * 1.4426950408889634f;

    // load Q tile (plain stores, swizzled)
    #pragma unroll
    for(int j = 0; j < 4; j++){
        int i = tid + j*256;
        int r = i >> 3, ch = i & 7;
        unsigned o = SWZ(r*128 + ch*16);
        *(uint4*)(sm + o) = *(const uint4*)(g_Qh + ib + (size_t)(i0 + r)*64 + ch*8);
    }

    int kt0 = 0;
    while(kt0 < 31 && c2 * (float)(1984 - 64*kt0) > 20.0f) kt0++;
    const int nch = 32 - kt0;

    const int lr = tid >> 3, lch = tid & 7;     // lr 0..31
    #define A_ISSUE(kt, st) do{ \
        const int j0_ = (kt) * 64; \
        const unsigned base_ = sb + 16384 + (st) * 16384; \
        _Pragma("unroll") \
        for(int j_ = 0; j_ < 2; j_++){ \
            int r_ = lr + j_*32; \
            unsigned o_ = SWZ(r_*128 + lch*16); \
            size_t gx_ = ib + (size_t)(j0_ + r_)*64 + lch*8; \
            cpa16(base_ + o_,        g_Kh  + gx_); \
            cpa16(base_ + 8192 + o_, g_Vsh + gx_); \
        } \
        CP_COMMIT(); \
    }while(0)

    A_ISSUE(kt0, 0);
    __syncthreads();   // Q visible

    const int rr  = (lane & 7) + ((lane >> 3) & 1) * 8;
    const int csl = lane >> 4;

    unsigned qh[4][4];
    #pragma unroll
    for(int ks = 0; ks < 4; ks++)
        ldsm4(qh[ks], sb + SWZ((w*16 + rr)*128 + (ks*2 + csl)*16));

    float o_[8][4];
    #pragma unroll
    for(int a=0;a<8;a++)
        #pragma unroll
        for(int e=0;e<4;e++) o_[a][e]=0.0f;
    float l0 = 0.0f, l1 = 0.0f;

    for(int ci = 0; ci < nch; ci++){
        const int kt = kt0 + ci;
        const int j0 = kt * 64;
        if(ci + 1 < nch){ A_ISSUE(kt + 1, (ci + 1) & 1); CP_WAIT1(); }
        else            { CP_WAIT0(); }
        __syncthreads();
        const unsigned base = sb + 16384 + (ci & 1) * 16384;

        // S = Q @ K^T  (pure fp16)
        float s_[8][4];
        #pragma unroll
        for(int a=0;a<8;a++)
            #pragma unroll
            for(int e=0;e<4;e++) s_[a][e]=0.0f;
        #pragma unroll
        for(int ks = 0; ks < 4; ks++){
            unsigned kbh[4][4];
            #pragma unroll
            for(int g = 0; g < 4; g++)
                ldsm4(kbh[g], base + SWZ((g*16 + rr)*128 + (ks*2 + csl)*16));
            #pragma unroll
            for(int g = 0; g < 4; g++)
                #pragma unroll
                for(int sub = 0; sub < 2; sub++)
                    mma16816(s_[g*2 + sub], qh[ks], kbh[g][sub], kbh[g][sub+2]);
        }

        // exp2 with analytic shift; build P fragments (fp16)
        unsigned ph[4][4];
        #pragma unroll
        for(int nt = 0; nt < 8; nt++){
            const float jb = (float)(j0 + nt*8 + (lane & 3)*2 - 2047);
            float p0 = ex2f(fmaf(c2, jb,        s_[nt][0]));
            float p1 = ex2f(fmaf(c2, jb + 1.0f, s_[nt][1]));
            float p2 = ex2f(fmaf(c2, jb,        s_[nt][2]));
            float p3 = ex2f(fmaf(c2, jb + 1.0f, s_[nt][3]));
            l0 += p0 + p1;
            l1 += p2 + p3;
            const int kk = nt >> 1, od = nt & 1;
            ph[kk][od ? 2 : 0] = packh(p0, p1);
            ph[kk][od ? 3 : 1] = packh(p2, p3);
        }

        // O += P @ V  (V stored [s][d]; B-fragments via ldmatrix.trans; fp16)
        #pragma unroll
        for(int kk = 0; kk < 4; kk++){
            unsigned vbh[4][4];
            #pragma unroll
            for(int g = 0; g < 4; g++)
                ldsm4t(vbh[g], base + 8192 + SWZ((kk*16 + rr)*128 + (g*2 + csl)*16));
            #pragma unroll
            for(int g = 0; g < 4; g++)
                #pragma unroll
                for(int sub = 0; sub < 2; sub++)
                    mma16816(o_[g*2 + sub], ph[kk], vbh[g][2*sub], vbh[g][2*sub+1]);
        }
        __syncthreads();
    }

    // reduce l within quads
    l0 += __shfl_xor_sync(0xffffffffu, l0, 1);
    l0 += __shfl_xor_sync(0xffffffffu, l0, 2);
    l1 += __shfl_xor_sync(0xffffffffu, l1, 1);
    l1 += __shfl_xor_sync(0xffffffffu, l1, 2);
    const float inv0 = 1.0f / l0, inv1 = 1.0f / l1;

    const int r0g = i0 + w*16 + (lane >> 2);
    float* op0 = out + ((size_t)b*2048 + r0g)*1024 + h*64 + (lane & 3)*2;
    float* op1 = out + ((size_t)b*2048 + r0g + 8)*1024 + h*64 + (lane & 3)*2;
    #pragma unroll
    for(int nt = 0; nt < 8; nt++){
        *(float2*)(op0 + nt*8) = make_float2(o_[nt][0]*inv0, o_[nt][1]*inv0);
        *(float2*)(op1 + nt*8) = make_float2(o_[nt][2]*inv1, o_[nt][3]*inv1);
    }
}

// ------------------------------- launch --------------------------------------
extern "C" void kernel_launch(void* const* d_in, const int* in_sizes, int n_in,
                              void* d_out, int out_size)
{
    const float* x = (const float*)d_in[0];
    const float* w = (const float*)d_in[1];
    float* out = (float*)d_out;
    (void)in_sizes; (void)n_in; (void)out_size;

    splitx_kernel<<<4096, 256>>>(x);
    splitw_kernel<<<dim3(48, 16), 256>>>(w);

    cudaFuncSetAttribute(gemm_kernel, cudaFuncAttributeMaxDynamicSharedMemorySize, GSM);
    gemm_kernel<<<dim3(24, 64), 256, GSM>>>();

    cudaFuncSetAttribute(attn_kernel, cudaFuncAttributeMaxDynamicSharedMemorySize, ASM);
    attn_kernel<<<dim3(16, 64), 256, ASM>>>(out);
}